// round 1
// baseline (speedup 1.0000x reference)
#include <cuda_runtime.h>
#include <math.h>

#define SEQ   8192
#define INP   512
#define HYP   1024
#define HIDN  4096
#define CHUNK 128
#define NCHUNK (SEQ/CHUNK)   // 64

// ---------------- scratch (static __device__, no allocations) ----------------
__device__ float g_h1[SEQ*HYP];
__device__ float g_t1[SEQ*HYP];
__device__ float g_t2[SEQ*HYP];
__device__ float g_h2[SEQ*HYP];
__device__ float g_h3[SEQ*HYP];
__device__ float g_B [SEQ*HIDN];
__device__ float g_G [SEQ*HIDN];
__device__ float g_Ac[NCHUNK*HIDN];
__device__ float g_Bc[NCHUNK*HIDN];
__device__ float g_Gb[(NCHUNK+1)*HIDN];

// ---------------- SGEMM: C[M,N] = A[M,K] @ W[N,K]^T + bias -------------------
// Both operands K-major (NT layout) -> coalesced along K.
// 128x128 block tile, 256 threads, 8x8 per-thread microtile, BK=8.
// Assumes M%128==0, N%128==0, K%8==0 (true for all shapes here).
__global__ __launch_bounds__(256, 2)
void sgemm_nt(const float* __restrict__ A, const float* __restrict__ W,
              const float* __restrict__ bias, float* __restrict__ C,
              int N, int K)
{
    __shared__ float As[8][128];
    __shared__ float Ws[8][128];

    const int tid  = threadIdx.x;
    const int bm   = blockIdx.y << 7;
    const int bn   = blockIdx.x << 7;
    const int lrow = tid >> 1;          // 0..127
    const int lk   = (tid & 1) << 2;    // 0 or 4

    const float* Ag = A + (size_t)(bm + lrow) * K + lk;
    const float* Wg = W + (size_t)(bn + lrow) * K + lk;

    const int tx = tid & 15, ty = tid >> 4;
    const int m0 = ty << 3, n0 = tx << 3;

    float acc[8][8];
#pragma unroll
    for (int i = 0; i < 8; i++)
#pragma unroll
        for (int j = 0; j < 8; j++) acc[i][j] = 0.f;

    for (int k0 = 0; k0 < K; k0 += 8) {
        float4 a4 = *(const float4*)(Ag + k0);
        float4 w4 = *(const float4*)(Wg + k0);
        __syncthreads();
        As[lk+0][lrow] = a4.x; As[lk+1][lrow] = a4.y;
        As[lk+2][lrow] = a4.z; As[lk+3][lrow] = a4.w;
        Ws[lk+0][lrow] = w4.x; Ws[lk+1][lrow] = w4.y;
        Ws[lk+2][lrow] = w4.z; Ws[lk+3][lrow] = w4.w;
        __syncthreads();
#pragma unroll
        for (int kk = 0; kk < 8; kk++) {
            float a[8], w[8];
            *(float4*)(a)   = *(const float4*)&As[kk][m0];
            *(float4*)(a+4) = *(const float4*)&As[kk][m0+4];
            *(float4*)(w)   = *(const float4*)&Ws[kk][n0];
            *(float4*)(w+4) = *(const float4*)&Ws[kk][n0+4];
#pragma unroll
            for (int i = 0; i < 8; i++)
#pragma unroll
                for (int j = 0; j < 8; j++)
                    acc[i][j] = fmaf(a[i], w[j], acc[i][j]);
        }
    }

    float bv[8];
    *(float4*)(bv)   = *(const float4*)&bias[bn + n0];
    *(float4*)(bv+4) = *(const float4*)&bias[bn + n0 + 4];
#pragma unroll
    for (int i = 0; i < 8; i++) {
        float* Crow = C + (size_t)(bm + m0 + i) * N + bn + n0;
        float4 o1 = make_float4(acc[i][0]+bv[0], acc[i][1]+bv[1],
                                acc[i][2]+bv[2], acc[i][3]+bv[3]);
        float4 o2 = make_float4(acc[i][4]+bv[4], acc[i][5]+bv[5],
                                acc[i][6]+bv[6], acc[i][7]+bv[7]);
        *(float4*)(Crow)     = o1;
        *(float4*)(Crow + 4) = o2;
    }
}

// ---------------- elementwise gates ------------------------------------------
__device__ __forceinline__ float sigmoidf_(float x) { return 1.f / (1.f + expf(-x)); }

// o = v * sigmoid(g)   (float4 vectorized; n4 = n/4)
__global__ void ew_mul_sig4(const float4* __restrict__ v, const float4* __restrict__ g,
                            float4* __restrict__ o, int n4)
{
    int i = blockIdx.x * blockDim.x + threadIdx.x;
    if (i < n4) {
        float4 vv = v[i], gg = g[i];
        o[i] = make_float4(vv.x * sigmoidf_(gg.x), vv.y * sigmoidf_(gg.y),
                           vv.z * sigmoidf_(gg.z), vv.w * sigmoidf_(gg.w));
    }
}

// o = t * sigmoid(t)   (silu; shared-weight final pair)
__global__ void ew_silu4(const float4* __restrict__ t, float4* __restrict__ o, int n4)
{
    int i = blockIdx.x * blockDim.x + threadIdx.x;
    if (i < n4) {
        float4 tt = t[i];
        o[i] = make_float4(tt.x * sigmoidf_(tt.x), tt.y * sigmoidf_(tt.y),
                           tt.z * sigmoidf_(tt.z), tt.w * sigmoidf_(tt.w));
    }
}

// ---------------- rotated-frame relu scan ------------------------------------
// Rotation: g_i[m] = h_i[(m+i) mod HIDN]  =>  g_i[m] = relu(b[i][(m+i)%HIDN] + g_{i-1}[m])
// 4096 independent chains; chunked max-plus scan for parallelism.

// Pass 1: per (chunk, lane) composition (A,B): x -> max(A, B + x)
__global__ void scan_pass1(const float* __restrict__ B,
                           float* __restrict__ Ac, float* __restrict__ Bc)
{
    int t    = blockIdx.x * blockDim.x + threadIdx.x;   // [0, NCHUNK*HIDN)
    int lane = t & (HIDN - 1);
    int chnk = t >> 12;                                 // HIDN = 2^12
    float Aa = -1e30f, Ss = 0.f;
    int base = chnk * CHUNK;
#pragma unroll 8
    for (int i = 0; i < CHUNK; i++) {
        int row = base + i;
        float b = B[(size_t)row * HIDN + ((lane + row) & (HIDN - 1))];
        Aa = fmaxf(0.f, b + Aa);
        Ss += b;
    }
    Ac[t] = Aa; Bc[t] = Ss;
}

// Combine: per-lane sequential over 64 chunks (tiny), produces entering states
__global__ void scan_combine(const float* __restrict__ hidden,
                             const float* __restrict__ Ac, const float* __restrict__ Bc,
                             float* __restrict__ Gb)
{
    int lane = blockIdx.x * blockDim.x + threadIdx.x;   // [0, HIDN)
    float gv = hidden[(lane - 1) & (HIDN - 1)];         // g_{-1}[m] = hidden[(m-1)%N]
    Gb[lane] = gv;
    for (int c = 0; c < NCHUNK; c++) {
        gv = fmaxf(Ac[c * HIDN + lane], Bc[c * HIDN + lane] + gv);
        Gb[(c + 1) * HIDN + lane] = gv;
    }
}

// Pass 2: replay each chunk exactly from its entering state; write outputs
__global__ void scan_pass2(const float* __restrict__ B, const float* __restrict__ Gb,
                           float* __restrict__ out, float* __restrict__ hlast, int write_h)
{
    int t    = blockIdx.x * blockDim.x + threadIdx.x;
    int lane = t & (HIDN - 1);
    int chnk = t >> 12;
    float gv = Gb[chnk * HIDN + lane];
    int base = chnk * CHUNK;
#pragma unroll 4
    for (int i = 0; i < CHUNK; i++) {
        int row = base + i;
        int col = (lane + row) & (HIDN - 1);
        gv = fmaxf(0.f, B[(size_t)row * HIDN + col] + gv);
        out[(size_t)row * HIDN + col] = gv;
    }
    // h_last[j] = g_{S-1}[(j-(S-1))%N]  =>  lane m writes h_last[(m-1)%N]
    if (write_h && chnk == NCHUNK - 1)
        hlast[(lane - 1) & (HIDN - 1)] = gv;
}

// ---------------- launch ------------------------------------------------------
extern "C" void kernel_launch(void* const* d_in, const int* in_sizes, int n_in,
                              void* d_out, int out_size)
{
    const float* x     = (const float*)d_in[0];
    const float* hidden= (const float*)d_in[1];
    const float* w_in  = (const float*)d_in[2];
    const float* b_in  = (const float*)d_in[3];
    const float* wg0   = (const float*)d_in[4];
    const float* bg0   = (const float*)d_in[5];
    const float* wg0g  = (const float*)d_in[6];
    const float* bg0g  = (const float*)d_in[7];
    const float* wg_sh = (const float*)d_in[8];
    const float* bg_sh = (const float*)d_in[9];
    const float* w_h   = (const float*)d_in[10];
    const float* b_h   = (const float*)d_in[11];
    const float* w2    = (const float*)d_in[12];
    const float* b2    = (const float*)d_in[13];

    float* out   = (float*)d_out;
    float* hlast = out + (size_t)SEQ * HIDN;
    int write_h  = (out_size >= SEQ * HIDN + HIDN) ? 1 : 0;

    float *h1, *t1, *t2, *h2, *h3, *B, *G, *Ac, *Bc, *Gb;
    cudaGetSymbolAddress((void**)&h1, g_h1);
    cudaGetSymbolAddress((void**)&t1, g_t1);
    cudaGetSymbolAddress((void**)&t2, g_t2);
    cudaGetSymbolAddress((void**)&h2, g_h2);
    cudaGetSymbolAddress((void**)&h3, g_h3);
    cudaGetSymbolAddress((void**)&B,  g_B);
    cudaGetSymbolAddress((void**)&G,  g_G);
    cudaGetSymbolAddress((void**)&Ac, g_Ac);
    cudaGetSymbolAddress((void**)&Bc, g_Bc);
    cudaGetSymbolAddress((void**)&Gb, g_Gb);

    const dim3 gHyp(HYP / 128, SEQ / 128);   // 8 x 64
    const dim3 gHid(HIDN / 128, SEQ / 128);  // 32 x 64

    // h1 = x @ w_in^T + b_in
    sgemm_nt<<<gHyp, 256>>>(x, w_in, b_in, h1, HYP, INP);
    // gln pair 0
    sgemm_nt<<<gHyp, 256>>>(h1, wg0,  bg0,  t1, HYP, HYP);
    sgemm_nt<<<gHyp, 256>>>(h1, wg0g, bg0g, t2, HYP, HYP);
    ew_mul_sig4<<<(SEQ*HYP/4 + 255)/256, 256>>>((const float4*)t1, (const float4*)t2,
                                                (float4*)h2, SEQ*HYP/4);
    // shared final pair: one GEMM + silu
    sgemm_nt<<<gHyp, 256>>>(h2, wg_sh, bg_sh, t1, HYP, HYP);
    ew_silu4<<<(SEQ*HYP/4 + 255)/256, 256>>>((const float4*)t1, (float4*)h3, SEQ*HYP/4);
    // B = (h3 @ w_h^T + b_h) * sigmoid(x @ w2^T + b2)
    sgemm_nt<<<gHid, 256>>>(h3, w_h, b_h, B, HIDN, HYP);
    sgemm_nt<<<gHid, 256>>>(x,  w2,  b2,  G, HIDN, INP);
    ew_mul_sig4<<<(SEQ*HIDN/4 + 255)/256, 256>>>((const float4*)B, (const float4*)G,
                                                 (float4*)B, SEQ*HIDN/4);
    // chunked rotated-frame scan
    scan_pass1<<<NCHUNK*HIDN/256, 256>>>(B, Ac, Bc);
    scan_combine<<<HIDN/256, 256>>>(hidden, Ac, Bc, Gb);
    scan_pass2<<<NCHUNK*HIDN/256, 256>>>(B, Gb, out, hlast, write_h);
}

// round 3
// speedup vs baseline: 2.3455x; 2.3455x over previous
#include <cuda_runtime.h>
#include <cuda_bf16.h>
#include <stdint.h>
#include <math.h>

#define SEQ   8192
#define INP   512
#define HYP   1024
#define HIDN  4096
#define CHUNK 128
#define NCHUNK (SEQ/CHUNK)   // 64

// ---------------- scratch (static __device__, no allocations) ----------------
__device__ __nv_bfloat16 g_xhi [SEQ*INP],  g_xlo [SEQ*INP];
__device__ __nv_bfloat16 g_h1hi[SEQ*HYP],  g_h1lo[SEQ*HYP];
__device__ __nv_bfloat16 g_h2hi[SEQ*HYP],  g_h2lo[SEQ*HYP];
__device__ __nv_bfloat16 g_h3hi[SEQ*HYP],  g_h3lo[SEQ*HYP];
__device__ __nv_bfloat16 g_winhi[HYP*INP], g_winlo[HYP*INP];
__device__ __nv_bfloat16 g_wg0hi[HYP*HYP], g_wg0lo[HYP*HYP];
__device__ __nv_bfloat16 g_wgGhi[HYP*HYP], g_wgGlo[HYP*HYP];
__device__ __nv_bfloat16 g_wshhi[HYP*HYP], g_wshlo[HYP*HYP];
__device__ __nv_bfloat16 g_whhi[HIDN*HYP], g_whlo[HIDN*HYP];
__device__ __nv_bfloat16 g_w2hi[HIDN*INP], g_w2lo[HIDN*INP];
__device__ float g_t2[SEQ*HYP];
__device__ float g_G [SEQ*HIDN];
__device__ float g_B [SEQ*HIDN];
__device__ float g_Ac[NCHUNK*HIDN];
__device__ float g_Bc[NCHUNK*HIDN];
__device__ float g_Gb[(NCHUNK+1)*HIDN];

// ---------------- PTX helpers (sm_100-portable only) --------------------------
__device__ __forceinline__ uint32_t smem_u32(const void* p) {
    uint32_t a;
    asm("{ .reg .u64 t; cvta.to.shared.u64 t, %1; cvt.u32.u64 %0, t; }" : "=r"(a) : "l"(p));
    return a;
}
__device__ __forceinline__ void cp16(uint32_t dst, const void* src) {
    asm volatile("cp.async.cg.shared.global [%0], [%1], 16;" :: "r"(dst), "l"(src));
}
__device__ __forceinline__ void cp_commit() { asm volatile("cp.async.commit_group;"); }
template <int N> __device__ __forceinline__ void cp_wait() {
    asm volatile("cp.async.wait_group %0;" :: "n"(N));
}
__device__ __forceinline__ void ldm4(uint32_t* r, uint32_t addr) {
    asm volatile("ldmatrix.sync.aligned.m8n8.x4.shared.b16 {%0,%1,%2,%3}, [%4];"
                 : "=r"(r[0]), "=r"(r[1]), "=r"(r[2]), "=r"(r[3]) : "r"(addr));
}
__device__ __forceinline__ void mma16816(float* d, const uint32_t* a, const uint32_t* b) {
    asm volatile(
        "mma.sync.aligned.m16n8k16.row.col.f32.bf16.bf16.f32 "
        "{%0,%1,%2,%3}, {%4,%5,%6,%7}, {%8,%9}, {%0,%1,%2,%3};"
        : "+f"(d[0]), "+f"(d[1]), "+f"(d[2]), "+f"(d[3])
        : "r"(a[0]), "r"(a[1]), "r"(a[2]), "r"(a[3]), "r"(b[0]), "r"(b[1]));
}

// ---------------- tcgen05-free bf16x3 GEMM ------------------------------------
// C[M,N] = (Ahi+Alo)[M,K] @ (Whi+Wlo)[N,K]^T + bias  (3 products, fp32 accum)
// 128x128 block tile, BK=64, 2-stage cp.async, 8 warps (2x4), 64x32 warp tiles.
#define BM 128
#define BN 128
#define BKE 64                 // bf16 elems per K-stage
#define ROWB 144               // 128B data + 16B pad (bank-conflict-free)
#define STAGE (128*ROWB)       // 18432 B per operand per stage
#define SMEM_DYN (4*STAGE)     // 73728 B

#define M_FP32       0
#define M_SPLIT      1
#define M_GATE_SPLIT 2
#define M_SILU_SPLIT 3
#define M_GATE_FP32  4

__device__ __forceinline__ float sigm(float x) { return 1.f / (1.f + expf(-x)); }

__global__ __launch_bounds__(256, 2)
void gemm_mma(const __nv_bfloat16* __restrict__ Ahi, const __nv_bfloat16* __restrict__ Alo,
              const __nv_bfloat16* __restrict__ Whi, const __nv_bfloat16* __restrict__ Wlo,
              const float* __restrict__ bias, const float* __restrict__ aux,
              int N, int K, int mode,
              float* __restrict__ Cf,
              __nv_bfloat16* __restrict__ Chi, __nv_bfloat16* __restrict__ Clo)
{
    extern __shared__ char dsmem[];
    const int tid = threadIdx.x, lane = tid & 31, wid = tid >> 5;
    const int warp_m = wid >> 2, warp_n = wid & 3;        // 2 x 4 warp grid
    const int bm = blockIdx.y * BM, bn = blockIdx.x * BN;
    const uint32_t sbase = smem_u32(dsmem);

    float acc[4][4][4];
#pragma unroll
    for (int i = 0; i < 4; i++)
#pragma unroll
        for (int j = 0; j < 4; j++)
#pragma unroll
            for (int q = 0; q < 4; q++) acc[i][j][q] = 0.f;

    // ldmatrix per-lane offsets (stage/k-step independent parts)
    uint32_t aoff[4], boff[2];
    {
        int rA   = (lane & 7) + ((lane >> 3) & 1) * 8;    // row within 16
        int ksA  = (lane >> 4) & 1;                        // +16B for k+8
#pragma unroll
        for (int mf = 0; mf < 4; mf++)
            aoff[mf] = (uint32_t)((warp_m * 64 + mf * 16 + rA) * ROWB + ksA * 16);
        int rB   = (lane & 7) + ((lane >> 4) & 1) * 8;    // n-row within 16
        int ksB  = (lane >> 3) & 1;
#pragma unroll
        for (int g = 0; g < 2; g++)
            boff[g] = (uint32_t)((warp_n * 32 + g * 16 + rB) * ROWB + ksB * 16);
    }

    const int spt = K / BKE;          // stages per term
    const int total = 3 * spt;

    // stage loader: 1024 16B-chunks per operand, 4 per thread per operand
    auto load_stage = [&](const __nv_bfloat16* Ap, const __nv_bfloat16* Wp,
                          int k0, int bufidx) {
        uint32_t dA = sbase + (uint32_t)bufidx * 2u * STAGE;
        uint32_t dB = dA + STAGE;
#pragma unroll
        for (int i = 0; i < 4; i++) {
            int c = i * 256 + tid;            // 0..1023
            int r = c >> 3, seg = c & 7;
            uint32_t o = (uint32_t)(r * ROWB + seg * 16);
            cp16(dA + o, Ap + (size_t)(bm + r) * K + k0 + seg * 8);
            cp16(dB + o, Wp + (size_t)(bn + r) * K + k0 + seg * 8);
        }
    };

    load_stage(Ahi, Whi, 0, 0);
    cp_commit();

    for (int s = 0; s < total; s++) {
        const int buf = s & 1;
        if (s + 1 < total) {
            const int s1 = s + 1;
            const int t  = s1 / spt;
            const int k0 = (s1 % spt) * BKE;
            const __nv_bfloat16* Ap = (t == 2) ? Alo : Ahi;
            const __nv_bfloat16* Wp = (t == 1) ? Wlo : Whi;
            load_stage(Ap, Wp, k0, buf ^ 1);
            cp_commit();
            cp_wait<1>();
        } else {
            cp_wait<0>();
        }
        __syncthreads();

        const uint32_t sA = sbase + (uint32_t)buf * 2u * STAGE;
        const uint32_t sB = sA + STAGE;
#pragma unroll
        for (int ks = 0; ks < 4; ks++) {
            uint32_t ar[16], br[8];
#pragma unroll
            for (int mf = 0; mf < 4; mf++)
                ldm4(ar + mf * 4, sA + aoff[mf] + ks * 32);
            ldm4(br,     sB + boff[0] + ks * 32);
            ldm4(br + 4, sB + boff[1] + ks * 32);
#pragma unroll
            for (int mf = 0; mf < 4; mf++)
#pragma unroll
                for (int nf = 0; nf < 4; nf++)
                    mma16816(acc[mf][nf], ar + mf * 4, br + nf * 2);
        }
        __syncthreads();
    }

    // ------------- fused epilogue: direct coalesced-sector global stores -------
    float2 bv[4];
#pragma unroll
    for (int nf = 0; nf < 4; nf++)
        bv[nf] = *(const float2*)&bias[bn + warp_n * 32 + nf * 8 + (lane & 3) * 2];

#pragma unroll
    for (int mf = 0; mf < 4; mf++) {
#pragma unroll
        for (int h = 0; h < 2; h++) {
            const int row = bm + warp_m * 64 + mf * 16 + (lane >> 2) + h * 8;
#pragma unroll
            for (int nf = 0; nf < 4; nf++) {
                const int col = bn + warp_n * 32 + nf * 8 + (lane & 3) * 2;
                const size_t off = (size_t)row * N + col;
                float v0 = acc[mf][nf][h * 2 + 0] + bv[nf].x;
                float v1 = acc[mf][nf][h * 2 + 1] + bv[nf].y;
                if (mode == M_GATE_SPLIT || mode == M_GATE_FP32) {
                    float2 g = *(const float2*)&aux[off];
                    v0 *= sigm(g.x); v1 *= sigm(g.y);
                } else if (mode == M_SILU_SPLIT) {
                    v0 *= sigm(v0);  v1 *= sigm(v1);
                }
                if (mode == M_FP32 || mode == M_GATE_FP32) {
                    *(float2*)&Cf[off] = make_float2(v0, v1);
                } else {
                    __nv_bfloat16 h0 = __float2bfloat16(v0);
                    __nv_bfloat16 h1 = __float2bfloat16(v1);
                    __nv_bfloat162 hp; hp.x = h0; hp.y = h1;
                    *(__nv_bfloat162*)&Chi[off] = hp;
                    __nv_bfloat162 lp;
                    lp.x = __float2bfloat16(v0 - __bfloat162float(h0));
                    lp.y = __float2bfloat16(v1 - __bfloat162float(h1));
                    *(__nv_bfloat162*)&Clo[off] = lp;
                }
            }
        }
    }
}

// ---------------- fp32 -> bf16 hi/lo split ------------------------------------
__global__ void split_bf16(const float* __restrict__ in,
                           __nv_bfloat16* __restrict__ hi, __nv_bfloat16* __restrict__ lo,
                           int n)
{
    int i = blockIdx.x * blockDim.x + threadIdx.x;
    if (i < n) {
        float v = in[i];
        __nv_bfloat16 h = __float2bfloat16(v);
        hi[i] = h;
        lo[i] = __float2bfloat16(v - __bfloat162float(h));
    }
}

// ---------------- rotated-frame relu scan (validated in R1) -------------------
__global__ void scan_pass1(const float* __restrict__ B,
                           float* __restrict__ Ac, float* __restrict__ Bc)
{
    int t    = blockIdx.x * blockDim.x + threadIdx.x;
    int lane = t & (HIDN - 1);
    int chnk = t >> 12;
    float Aa = -1e30f, Ss = 0.f;
    int base = chnk * CHUNK;
#pragma unroll 8
    for (int i = 0; i < CHUNK; i++) {
        int row = base + i;
        float b = B[(size_t)row * HIDN + ((lane + row) & (HIDN - 1))];
        Aa = fmaxf(0.f, b + Aa);
        Ss += b;
    }
    Ac[t] = Aa; Bc[t] = Ss;
}

__global__ void scan_combine(const float* __restrict__ hidden,
                             const float* __restrict__ Ac, const float* __restrict__ Bc,
                             float* __restrict__ Gb)
{
    int lane = blockIdx.x * blockDim.x + threadIdx.x;
    float gv = hidden[(lane - 1) & (HIDN - 1)];
    Gb[lane] = gv;
    for (int c = 0; c < NCHUNK; c++) {
        gv = fmaxf(Ac[c * HIDN + lane], Bc[c * HIDN + lane] + gv);
        Gb[(c + 1) * HIDN + lane] = gv;
    }
}

__global__ void scan_pass2(const float* __restrict__ B, const float* __restrict__ Gb,
                           float* __restrict__ out, float* __restrict__ hlast, int write_h)
{
    int t    = blockIdx.x * blockDim.x + threadIdx.x;
    int lane = t & (HIDN - 1);
    int chnk = t >> 12;
    float gv = Gb[chnk * HIDN + lane];
    int base = chnk * CHUNK;
#pragma unroll 4
    for (int i = 0; i < CHUNK; i++) {
        int row = base + i;
        int col = (lane + row) & (HIDN - 1);
        gv = fmaxf(0.f, B[(size_t)row * HIDN + col] + gv);
        out[(size_t)row * HIDN + col] = gv;
    }
    if (write_h && chnk == NCHUNK - 1)
        hlast[(lane - 1) & (HIDN - 1)] = gv;
}

// ---------------- launch ------------------------------------------------------
extern "C" void kernel_launch(void* const* d_in, const int* in_sizes, int n_in,
                              void* d_out, int out_size)
{
    const float* x      = (const float*)d_in[0];
    const float* hidden = (const float*)d_in[1];
    const float* w_in   = (const float*)d_in[2];
    const float* b_in   = (const float*)d_in[3];
    const float* wg0    = (const float*)d_in[4];
    const float* bg0    = (const float*)d_in[5];
    const float* wg0g   = (const float*)d_in[6];
    const float* bg0g   = (const float*)d_in[7];
    const float* wg_sh  = (const float*)d_in[8];
    const float* bg_sh  = (const float*)d_in[9];
    const float* w_h    = (const float*)d_in[10];
    const float* b_h    = (const float*)d_in[11];
    const float* w2     = (const float*)d_in[12];
    const float* b2     = (const float*)d_in[13];

    float* out   = (float*)d_out;
    float* hlast = out + (size_t)SEQ * HIDN;
    int write_h  = (out_size >= SEQ * HIDN + HIDN) ? 1 : 0;

    cudaFuncSetAttribute(gemm_mma, cudaFuncAttributeMaxDynamicSharedMemorySize, SMEM_DYN);

    __nv_bfloat16 *xhi, *xlo, *h1hi, *h1lo, *h2hi, *h2lo, *h3hi, *h3lo;
    __nv_bfloat16 *winhi, *winlo, *wg0hi, *wg0lo, *wgGhi, *wgGlo, *wshhi, *wshlo, *whhi, *whlo, *w2hi, *w2lo;
    float *t2, *G, *B, *Ac, *Bc, *Gb;
    cudaGetSymbolAddress((void**)&xhi, g_xhi);   cudaGetSymbolAddress((void**)&xlo, g_xlo);
    cudaGetSymbolAddress((void**)&h1hi, g_h1hi); cudaGetSymbolAddress((void**)&h1lo, g_h1lo);
    cudaGetSymbolAddress((void**)&h2hi, g_h2hi); cudaGetSymbolAddress((void**)&h2lo, g_h2lo);
    cudaGetSymbolAddress((void**)&h3hi, g_h3hi); cudaGetSymbolAddress((void**)&h3lo, g_h3lo);
    cudaGetSymbolAddress((void**)&winhi, g_winhi); cudaGetSymbolAddress((void**)&winlo, g_winlo);
    cudaGetSymbolAddress((void**)&wg0hi, g_wg0hi); cudaGetSymbolAddress((void**)&wg0lo, g_wg0lo);
    cudaGetSymbolAddress((void**)&wgGhi, g_wgGhi); cudaGetSymbolAddress((void**)&wgGlo, g_wgGlo);
    cudaGetSymbolAddress((void**)&wshhi, g_wshhi); cudaGetSymbolAddress((void**)&wshlo, g_wshlo);
    cudaGetSymbolAddress((void**)&whhi, g_whhi);   cudaGetSymbolAddress((void**)&whlo, g_whlo);
    cudaGetSymbolAddress((void**)&w2hi, g_w2hi);   cudaGetSymbolAddress((void**)&w2lo, g_w2lo);
    cudaGetSymbolAddress((void**)&t2, g_t2);
    cudaGetSymbolAddress((void**)&G, g_G);
    cudaGetSymbolAddress((void**)&B, g_B);
    cudaGetSymbolAddress((void**)&Ac, g_Ac);
    cudaGetSymbolAddress((void**)&Bc, g_Bc);
    cudaGetSymbolAddress((void**)&Gb, g_Gb);

    // splits: x + all weights
    split_bf16<<<(SEQ*INP  + 255)/256, 256>>>(x,     xhi,   xlo,   SEQ*INP);
    split_bf16<<<(HYP*INP  + 255)/256, 256>>>(w_in,  winhi, winlo, HYP*INP);
    split_bf16<<<(HYP*HYP  + 255)/256, 256>>>(wg0,   wg0hi, wg0lo, HYP*HYP);
    split_bf16<<<(HYP*HYP  + 255)/256, 256>>>(wg0g,  wgGhi, wgGlo, HYP*HYP);
    split_bf16<<<(HYP*HYP  + 255)/256, 256>>>(wg_sh, wshhi, wshlo, HYP*HYP);
    split_bf16<<<(HIDN*HYP + 255)/256, 256>>>(w_h,   whhi,  whlo,  HIDN*HYP);
    split_bf16<<<(HIDN*INP + 255)/256, 256>>>(w2,    w2hi,  w2lo,  HIDN*INP);

    const dim3 gHyp(HYP / BN, SEQ / BM);    // 8 x 64
    const dim3 gHid(HIDN / BN, SEQ / BM);   // 32 x 64

    // h1 = x @ w_in^T + b_in                       -> split
    gemm_mma<<<gHyp, 256, SMEM_DYN>>>(xhi, xlo, winhi, winlo, b_in, nullptr,
                                      HYP, INP, M_SPLIT, nullptr, h1hi, h1lo);
    // t2 = h1 @ wg0g^T + bg0g                      -> fp32
    gemm_mma<<<gHyp, 256, SMEM_DYN>>>(h1hi, h1lo, wgGhi, wgGlo, bg0g, nullptr,
                                      HYP, HYP, M_FP32, t2, nullptr, nullptr);
    // h2 = (h1 @ wg0^T + bg0) * sigmoid(t2)        -> split
    gemm_mma<<<gHyp, 256, SMEM_DYN>>>(h1hi, h1lo, wg0hi, wg0lo, bg0, t2,
                                      HYP, HYP, M_GATE_SPLIT, nullptr, h2hi, h2lo);
    // h3 = silu(h2 @ wg_sh^T + bg_sh)              -> split
    gemm_mma<<<gHyp, 256, SMEM_DYN>>>(h2hi, h2lo, wshhi, wshlo, bg_sh, nullptr,
                                      HYP, HYP, M_SILU_SPLIT, nullptr, h3hi, h3lo);
    // G = x @ w2^T + b2                            -> fp32
    gemm_mma<<<gHid, 256, SMEM_DYN>>>(xhi, xlo, w2hi, w2lo, b2, nullptr,
                                      HIDN, INP, M_FP32, G, nullptr, nullptr);
    // B = (h3 @ w_h^T + b_h) * sigmoid(G)          -> fp32
    gemm_mma<<<gHid, 256, SMEM_DYN>>>(h3hi, h3lo, whhi, whlo, b_h, G,
                                      HIDN, HYP, M_GATE_FP32, B, nullptr, nullptr);

    // chunked rotated-frame scan
    scan_pass1 <<<NCHUNK*HIDN/256, 256>>>(B, Ac, Bc);
    scan_combine<<<HIDN/256, 256>>>(hidden, Ac, Bc, Gb);
    scan_pass2 <<<NCHUNK*HIDN/256, 256>>>(B, Gb, out, hlast, write_h);
}

// round 5
// speedup vs baseline: 3.7731x; 1.6086x over previous
#include <cuda_runtime.h>
#include <cuda_fp16.h>
#include <stdint.h>
#include <math.h>

#define SEQ   8192
#define INP   512
#define HYP   1024
#define HIDN  4096
#define CHUNK 128
#define NCHUNK (SEQ/CHUNK)   // 64

// ---------------- scratch (static __device__, no allocations) ----------------
__device__ __half g_xh  [SEQ*INP];
__device__ __half g_h1h [SEQ*HYP];
__device__ __half g_h2h [SEQ*HYP];
__device__ __half g_h3h [SEQ*HYP];
__device__ __half g_t2h [SEQ*HYP];        // gate values (fp16 ok)
__device__ __half g_Gh  [SEQ*HIDN];
__device__ __half g_winhi[HYP*INP], g_winlo[HYP*INP];
__device__ __half g_wg0hi[HYP*HYP], g_wg0lo[HYP*HYP];
__device__ __half g_wgGh [HYP*HYP];       // gate weight, single fp16
__device__ __half g_wshhi[HYP*HYP], g_wshlo[HYP*HYP];
__device__ __half g_whhi[HIDN*HYP], g_whlo[HIDN*HYP];
__device__ __half g_w2h [HIDN*INP];       // gate weight, single fp16
__device__ float g_B [SEQ*HIDN];
__device__ float g_Ac[NCHUNK*HIDN];
__device__ float g_Bc[NCHUNK*HIDN];
__device__ float g_Gb[(NCHUNK+1)*HIDN];

// ---------------- PTX helpers (sm_100-portable only) --------------------------
__device__ __forceinline__ uint32_t smem_u32(const void* p) {
    uint32_t a;
    asm("{ .reg .u64 t; cvta.to.shared.u64 t, %1; cvt.u32.u64 %0, t; }" : "=r"(a) : "l"(p));
    return a;
}
__device__ __forceinline__ void cp16(uint32_t dst, const void* src) {
    asm volatile("cp.async.cg.shared.global [%0], [%1], 16;" :: "r"(dst), "l"(src));
}
__device__ __forceinline__ void cp_commit() { asm volatile("cp.async.commit_group;"); }
template <int N> __device__ __forceinline__ void cp_wait() {
    asm volatile("cp.async.wait_group %0;" :: "n"(N));
}
__device__ __forceinline__ void ldm4(uint32_t* r, uint32_t addr) {
    asm volatile("ldmatrix.sync.aligned.m8n8.x4.shared.b16 {%0,%1,%2,%3}, [%4];"
                 : "=r"(r[0]), "=r"(r[1]), "=r"(r[2]), "=r"(r[3]) : "r"(addr));
}
__device__ __forceinline__ void mma16816(float* d, const uint32_t* a, const uint32_t* b) {
    asm volatile(
        "mma.sync.aligned.m16n8k16.row.col.f32.f16.f16.f32 "
        "{%0,%1,%2,%3}, {%4,%5,%6,%7}, {%8,%9}, {%0,%1,%2,%3};"
        : "+f"(d[0]), "+f"(d[1]), "+f"(d[2]), "+f"(d[3])
        : "r"(a[0]), "r"(a[1]), "r"(a[2]), "r"(a[3]), "r"(b[0]), "r"(b[1]));
}

// ---------------- fp16 GEMM: C[M,N] = A[M,K] @ (Whi[+Wlo])[N,K]^T + bias ------
// 128x128 block tile, BK=64, 2-stage cp.async, 8 warps (2x4), 64x32 warp tiles.
#define BM 128
#define BN 128
#define BKE 64
#define ROWB 144
#define STAGE (128*ROWB)         // 18432 B per operand per stage
#define SMEM_DYN (4*STAGE)       // 73728 B

// mode flags
#define F_OUT16 1
#define F_GATE  2
#define F_SILU  4

__device__ __forceinline__ float sigm(float x) { return 1.f / (1.f + expf(-x)); }

__global__ __launch_bounds__(256, 2)
void gemm_f16(const __half* __restrict__ A,
              const __half* __restrict__ Whi, const __half* __restrict__ Wlo,
              const float* __restrict__ bias, const __half* __restrict__ aux,
              int N, int K, int nterms, int mode,
              float* __restrict__ Cf, __half* __restrict__ Ch)
{
    extern __shared__ char dsmem[];
    const int tid = threadIdx.x, lane = tid & 31, wid = tid >> 5;
    const int warp_m = wid >> 2, warp_n = wid & 3;
    const int bm = blockIdx.y * BM, bn = blockIdx.x * BN;
    const uint32_t sbase = smem_u32(dsmem);

    float acc[4][4][4];
#pragma unroll
    for (int i = 0; i < 4; i++)
#pragma unroll
        for (int j = 0; j < 4; j++)
#pragma unroll
            for (int q = 0; q < 4; q++) acc[i][j][q] = 0.f;

    uint32_t aoff[4], boff[2];
    {
        int rA  = (lane & 7) + ((lane >> 3) & 1) * 8;
        int ksA = (lane >> 4) & 1;
#pragma unroll
        for (int mf = 0; mf < 4; mf++)
            aoff[mf] = (uint32_t)((warp_m * 64 + mf * 16 + rA) * ROWB + ksA * 16);
        int rB  = (lane & 7) + ((lane >> 4) & 1) * 8;
        int ksB = (lane >> 3) & 1;
#pragma unroll
        for (int g = 0; g < 2; g++)
            boff[g] = (uint32_t)((warp_n * 32 + g * 16 + rB) * ROWB + ksB * 16);
    }

    const int spt = K / BKE;
    const int total = nterms * spt;

    auto load_stage = [&](const __half* Wp, int k0, int bufidx) {
        uint32_t dA = sbase + (uint32_t)bufidx * 2u * STAGE;
        uint32_t dB = dA + STAGE;
#pragma unroll
        for (int i = 0; i < 4; i++) {
            int c = i * 256 + tid;
            int r = c >> 3, seg = c & 7;
            uint32_t o = (uint32_t)(r * ROWB + seg * 16);
            cp16(dA + o, A  + (size_t)(bm + r) * K + k0 + seg * 8);
            cp16(dB + o, Wp + (size_t)(bn + r) * K + k0 + seg * 8);
        }
    };

    load_stage(Whi, 0, 0);
    cp_commit();

    for (int s = 0; s < total; s++) {
        const int buf = s & 1;
        if (s + 1 < total) {
            const int s1 = s + 1;
            const __half* Wp = (s1 / spt == 1) ? Wlo : Whi;
            load_stage(Wp, (s1 % spt) * BKE, buf ^ 1);
            cp_commit();
            cp_wait<1>();
        } else {
            cp_wait<0>();
        }
        __syncthreads();

        const uint32_t sA = sbase + (uint32_t)buf * 2u * STAGE;
        const uint32_t sB = sA + STAGE;
#pragma unroll
        for (int ks = 0; ks < 4; ks++) {
            uint32_t br[8];
            ldm4(br,     sB + boff[0] + ks * 32);
            ldm4(br + 4, sB + boff[1] + ks * 32);
#pragma unroll
            for (int mf = 0; mf < 4; mf++) {
                uint32_t ar[4];
                ldm4(ar, sA + aoff[mf] + ks * 32);
#pragma unroll
                for (int nf = 0; nf < 4; nf++)
                    mma16816(acc[mf][nf], ar, br + nf * 2);
            }
        }
        __syncthreads();
    }

    // ------------- fused epilogue -------------
    float2 bv[4];
#pragma unroll
    for (int nf = 0; nf < 4; nf++)
        bv[nf] = *(const float2*)&bias[bn + warp_n * 32 + nf * 8 + (lane & 3) * 2];

#pragma unroll
    for (int mf = 0; mf < 4; mf++) {
#pragma unroll
        for (int h = 0; h < 2; h++) {
            const int row = bm + warp_m * 64 + mf * 16 + (lane >> 2) + h * 8;
#pragma unroll
            for (int nf = 0; nf < 4; nf++) {
                const int col = bn + warp_n * 32 + nf * 8 + (lane & 3) * 2;
                const size_t off = (size_t)row * N + col;
                float v0 = acc[mf][nf][h * 2 + 0] + bv[nf].x;
                float v1 = acc[mf][nf][h * 2 + 1] + bv[nf].y;
                if (mode & F_GATE) {
                    __half2 g = *(const __half2*)&aux[off];
                    v0 *= sigm(__half2float(g.x));
                    v1 *= sigm(__half2float(g.y));
                } else if (mode & F_SILU) {
                    v0 *= sigm(v0); v1 *= sigm(v1);
                }
                if (mode & F_OUT16) {
                    __half2 o; o.x = __float2half(v0); o.y = __float2half(v1);
                    *(__half2*)&Ch[off] = o;
                } else {
                    *(float2*)&Cf[off] = make_float2(v0, v1);
                }
            }
        }
    }
}

// ---------------- conversion / split kernels ----------------------------------
__global__ void cvt_f16(const float* __restrict__ in, __half* __restrict__ o, int n)
{
    int i = (blockIdx.x * blockDim.x + threadIdx.x) * 4;
    if (i < n) {
        float4 v = *(const float4*)&in[i];
        __half2 a; a.x = __float2half(v.x); a.y = __float2half(v.y);
        __half2 b; b.x = __float2half(v.z); b.y = __float2half(v.w);
        *(__half2*)&o[i]     = a;
        *(__half2*)&o[i + 2] = b;
    }
}

__global__ void split_f16(const float* __restrict__ in,
                          __half* __restrict__ hi, __half* __restrict__ lo, int n)
{
    int i = (blockIdx.x * blockDim.x + threadIdx.x) * 4;
    if (i < n) {
        float4 v = *(const float4*)&in[i];
        float vv[4] = {v.x, v.y, v.z, v.w};
        __half hh[4], ll[4];
#pragma unroll
        for (int q = 0; q < 4; q++) {
            hh[q] = __float2half(vv[q]);
            ll[q] = __float2half(vv[q] - __half2float(hh[q]));
        }
        *(__half2*)&hi[i]     = __halves2half2(hh[0], hh[1]);
        *(__half2*)&hi[i + 2] = __halves2half2(hh[2], hh[3]);
        *(__half2*)&lo[i]     = __halves2half2(ll[0], ll[1]);
        *(__half2*)&lo[i + 2] = __halves2half2(ll[2], ll[3]);
    }
}

// ---------------- rotated-frame relu scan (validated) -------------------------
__global__ void scan_pass1(const float* __restrict__ B,
                           float* __restrict__ Ac, float* __restrict__ Bc)
{
    int t    = blockIdx.x * blockDim.x + threadIdx.x;
    int lane = t & (HIDN - 1);
    int chnk = t >> 12;
    float Aa = -1e30f, Ss = 0.f;
    int base = chnk * CHUNK;
#pragma unroll 8
    for (int i = 0; i < CHUNK; i++) {
        int row = base + i;
        float b = B[(size_t)row * HIDN + ((lane + row) & (HIDN - 1))];
        Aa = fmaxf(0.f, b + Aa);
        Ss += b;
    }
    Ac[t] = Aa; Bc[t] = Ss;
}

__global__ void scan_combine(const float* __restrict__ hidden,
                             const float* __restrict__ Ac, const float* __restrict__ Bc,
                             float* __restrict__ Gb)
{
    int lane = blockIdx.x * blockDim.x + threadIdx.x;
    float gv = hidden[(lane - 1) & (HIDN - 1)];
    Gb[lane] = gv;
    for (int c = 0; c < NCHUNK; c++) {
        gv = fmaxf(Ac[c * HIDN + lane], Bc[c * HIDN + lane] + gv);
        Gb[(c + 1) * HIDN + lane] = gv;
    }
}

__global__ void scan_pass2(const float* __restrict__ B, const float* __restrict__ Gb,
                           float* __restrict__ out, float* __restrict__ hlast, int write_h)
{
    int t    = blockIdx.x * blockDim.x + threadIdx.x;
    int lane = t & (HIDN - 1);
    int chnk = t >> 12;
    float gv = Gb[chnk * HIDN + lane];
    int base = chnk * CHUNK;
#pragma unroll 4
    for (int i = 0; i < CHUNK; i++) {
        int row = base + i;
        int col = (lane + row) & (HIDN - 1);
        gv = fmaxf(0.f, B[(size_t)row * HIDN + col] + gv);
        out[(size_t)row * HIDN + col] = gv;
    }
    if (write_h && chnk == NCHUNK - 1)
        hlast[(lane - 1) & (HIDN - 1)] = gv;
}

// ---------------- launch ------------------------------------------------------
extern "C" void kernel_launch(void* const* d_in, const int* in_sizes, int n_in,
                              void* d_out, int out_size)
{
    const float* x      = (const float*)d_in[0];
    const float* hidden = (const float*)d_in[1];
    const float* w_in   = (const float*)d_in[2];
    const float* b_in   = (const float*)d_in[3];
    const float* wg0    = (const float*)d_in[4];
    const float* bg0    = (const float*)d_in[5];
    const float* wg0g   = (const float*)d_in[6];
    const float* bg0g   = (const float*)d_in[7];
    const float* wg_sh  = (const float*)d_in[8];
    const float* bg_sh  = (const float*)d_in[9];
    const float* w_h    = (const float*)d_in[10];
    const float* b_h    = (const float*)d_in[11];
    const float* w2     = (const float*)d_in[12];
    const float* b2     = (const float*)d_in[13];

    float* out   = (float*)d_out;
    float* hlast = out + (size_t)SEQ * HIDN;
    int write_h  = (out_size >= SEQ * HIDN + HIDN) ? 1 : 0;

    cudaFuncSetAttribute(gemm_f16, cudaFuncAttributeMaxDynamicSharedMemorySize, SMEM_DYN);

    __half *xh, *h1h, *h2h, *h3h, *t2h, *Gh;
    __half *winhi, *winlo, *wg0hi, *wg0lo, *wgGh, *wshhi, *wshlo, *whhi, *whlo, *w2h;
    float *B, *Ac, *Bc, *Gb;
    cudaGetSymbolAddress((void**)&xh,  g_xh);
    cudaGetSymbolAddress((void**)&h1h, g_h1h);
    cudaGetSymbolAddress((void**)&h2h, g_h2h);
    cudaGetSymbolAddress((void**)&h3h, g_h3h);
    cudaGetSymbolAddress((void**)&t2h, g_t2h);
    cudaGetSymbolAddress((void**)&Gh,  g_Gh);
    cudaGetSymbolAddress((void**)&winhi, g_winhi); cudaGetSymbolAddress((void**)&winlo, g_winlo);
    cudaGetSymbolAddress((void**)&wg0hi, g_wg0hi); cudaGetSymbolAddress((void**)&wg0lo, g_wg0lo);
    cudaGetSymbolAddress((void**)&wgGh,  g_wgGh);
    cudaGetSymbolAddress((void**)&wshhi, g_wshhi); cudaGetSymbolAddress((void**)&wshlo, g_wshlo);
    cudaGetSymbolAddress((void**)&whhi,  g_whhi);  cudaGetSymbolAddress((void**)&whlo,  g_whlo);
    cudaGetSymbolAddress((void**)&w2h,   g_w2h);
    cudaGetSymbolAddress((void**)&B,  g_B);
    cudaGetSymbolAddress((void**)&Ac, g_Ac);
    cudaGetSymbolAddress((void**)&Bc, g_Bc);
    cudaGetSymbolAddress((void**)&Gb, g_Gb);

    // conversions / splits
    cvt_f16  <<<(SEQ*INP/4  + 255)/256, 256>>>(x,     xh,  SEQ*INP);
    split_f16<<<(HYP*INP/4  + 255)/256, 256>>>(w_in,  winhi, winlo, HYP*INP);
    split_f16<<<(HYP*HYP/4  + 255)/256, 256>>>(wg0,   wg0hi, wg0lo, HYP*HYP);
    cvt_f16  <<<(HYP*HYP/4  + 255)/256, 256>>>(wg0g,  wgGh, HYP*HYP);
    split_f16<<<(HYP*HYP/4  + 255)/256, 256>>>(wg_sh, wshhi, wshlo, HYP*HYP);
    split_f16<<<(HIDN*HYP/4 + 255)/256, 256>>>(w_h,   whhi,  whlo,  HIDN*HYP);
    cvt_f16  <<<(HIDN*INP/4 + 255)/256, 256>>>(w2,    w2h, HIDN*INP);

    const dim3 gHyp(HYP / BN, SEQ / BM);    // 8 x 64
    const dim3 gHid(HIDN / BN, SEQ / BM);   // 32 x 64

    // h1 = x @ w_in^T + b_in                      (2 terms -> f16)
    gemm_f16<<<gHyp, 256, SMEM_DYN>>>(xh, winhi, winlo, b_in, nullptr,
                                      HYP, INP, 2, F_OUT16, nullptr, h1h);
    // t2 = h1 @ wg0g^T + bg0g                     (1 term gate -> f16)
    gemm_f16<<<gHyp, 256, SMEM_DYN>>>(h1h, wgGh, nullptr, bg0g, nullptr,
                                      HYP, HYP, 1, F_OUT16, nullptr, t2h);
    // h2 = (h1 @ wg0^T + bg0) * sigmoid(t2)       (2 terms -> f16)
    gemm_f16<<<gHyp, 256, SMEM_DYN>>>(h1h, wg0hi, wg0lo, bg0, t2h,
                                      HYP, HYP, 2, F_OUT16 | F_GATE, nullptr, h2h);
    // h3 = silu(h2 @ wg_sh^T + bg_sh)             (2 terms -> f16)
    gemm_f16<<<gHyp, 256, SMEM_DYN>>>(h2h, wshhi, wshlo, bg_sh, nullptr,
                                      HYP, HYP, 2, F_OUT16 | F_SILU, nullptr, h3h);
    // G = x @ w2^T + b2                           (1 term gate -> f16)
    gemm_f16<<<gHid, 256, SMEM_DYN>>>(xh, w2h, nullptr, b2, nullptr,
                                      HIDN, INP, 1, F_OUT16, nullptr, Gh);
    // B = (h3 @ w_h^T + b_h) * sigmoid(G)         (2 terms -> f32)
    gemm_f16<<<gHid, 256, SMEM_DYN>>>(h3h, whhi, whlo, b_h, Gh,
                                      HIDN, HYP, 2, F_GATE, B, nullptr);

    // chunked rotated-frame scan
    scan_pass1 <<<NCHUNK*HIDN/256, 256>>>(B, Ac, Bc);
    scan_combine<<<HIDN/256, 256>>>(hidden, Ac, Bc, Gb);
    scan_pass2 <<<NCHUNK*HIDN/256, 256>>>(B, Gb, out, hlast, write_h);
}

// round 6
// speedup vs baseline: 5.1535x; 1.3659x over previous
#include <cuda_runtime.h>
#include <cuda_fp16.h>
#include <stdint.h>
#include <math.h>

#define SEQ   8192
#define INP   512
#define HYP   1024
#define HIDN  4096
#define CHUNK 128
#define NCHUNK (SEQ/CHUNK)   // 64

// ---------------- scratch (static __device__, no allocations) ----------------
__device__ __half g_xh  [SEQ*INP];
__device__ __half g_h1h [SEQ*HYP];
__device__ __half g_h2h [SEQ*HYP];
__device__ __half g_h3h [SEQ*HYP];
__device__ __half g_t2h [SEQ*HYP];
__device__ __half g_Gh  [SEQ*HIDN];
__device__ __half g_winhi[HYP*INP], g_winlo[HYP*INP];   // h1 keeps 2-term
__device__ __half g_wg0h [HYP*HYP];      // demoted to 1-term
__device__ __half g_wgGh [HYP*HYP];      // gate, 1-term
__device__ __half g_wshh [HYP*HYP];      // demoted to 1-term
__device__ __half g_whh  [HIDN*HYP];     // demoted to 1-term
__device__ __half g_w2h  [HIDN*INP];     // gate, 1-term
__device__ float g_B [SEQ*HIDN];
__device__ float g_Ac[NCHUNK*HIDN];
__device__ float g_Bc[NCHUNK*HIDN];
__device__ float g_Gb[(NCHUNK+1)*HIDN];

// ---------------- PTX helpers (sm_100-portable only) --------------------------
__device__ __forceinline__ uint32_t smem_u32(const void* p) {
    uint32_t a;
    asm("{ .reg .u64 t; cvta.to.shared.u64 t, %1; cvt.u32.u64 %0, t; }" : "=r"(a) : "l"(p));
    return a;
}
__device__ __forceinline__ void cp16(uint32_t dst, const void* src) {
    asm volatile("cp.async.cg.shared.global [%0], [%1], 16;" :: "r"(dst), "l"(src));
}
__device__ __forceinline__ void cp_commit() { asm volatile("cp.async.commit_group;"); }
template <int N> __device__ __forceinline__ void cp_wait() {
    asm volatile("cp.async.wait_group %0;" :: "n"(N));
}
__device__ __forceinline__ void ldm4(uint32_t* r, uint32_t addr) {
    asm volatile("ldmatrix.sync.aligned.m8n8.x4.shared.b16 {%0,%1,%2,%3}, [%4];"
                 : "=r"(r[0]), "=r"(r[1]), "=r"(r[2]), "=r"(r[3]) : "r"(addr));
}
__device__ __forceinline__ void mma16816(float* d, const uint32_t* a, const uint32_t* b) {
    asm volatile(
        "mma.sync.aligned.m16n8k16.row.col.f32.f16.f16.f32 "
        "{%0,%1,%2,%3}, {%4,%5,%6,%7}, {%8,%9}, {%0,%1,%2,%3};"
        : "+f"(d[0]), "+f"(d[1]), "+f"(d[2]), "+f"(d[3])
        : "r"(a[0]), "r"(a[1]), "r"(a[2]), "r"(a[3]), "r"(b[0]), "r"(b[1]));
}

// ---------------- fp16 GEMM: C[M,N] = A[M,K] @ (Whi[+Wlo])[N,K]^T + bias ------
#define BM 128
#define BN 128
#define BKE 64
#define ROWB 144
#define STAGE (128*ROWB)
#define SMEM_DYN (4*STAGE)       // 73728 B

#define F_OUT16 1
#define F_GATE  2
#define F_SILU  4

__device__ __forceinline__ float sigm(float x) { return 1.f / (1.f + expf(-x)); }

__global__ __launch_bounds__(256, 2)
void gemm_f16(const __half* __restrict__ A,
              const __half* __restrict__ Whi, const __half* __restrict__ Wlo,
              const float* __restrict__ bias, const __half* __restrict__ aux,
              int N, int K, int nterms, int mode,
              float* __restrict__ Cf, __half* __restrict__ Ch)
{
    extern __shared__ char dsmem[];
    const int tid = threadIdx.x, lane = tid & 31, wid = tid >> 5;
    const int warp_m = wid >> 2, warp_n = wid & 3;
    const int bm = blockIdx.y * BM, bn = blockIdx.x * BN;
    const uint32_t sbase = smem_u32(dsmem);

    float acc[4][4][4];
#pragma unroll
    for (int i = 0; i < 4; i++)
#pragma unroll
        for (int j = 0; j < 4; j++)
#pragma unroll
            for (int q = 0; q < 4; q++) acc[i][j][q] = 0.f;

    uint32_t aoff[4], boff[2];
    {
        int rA  = (lane & 7) + ((lane >> 3) & 1) * 8;
        int ksA = (lane >> 4) & 1;
#pragma unroll
        for (int mf = 0; mf < 4; mf++)
            aoff[mf] = (uint32_t)((warp_m * 64 + mf * 16 + rA) * ROWB + ksA * 16);
        int rB  = (lane & 7) + ((lane >> 4) & 1) * 8;
        int ksB = (lane >> 3) & 1;
#pragma unroll
        for (int g = 0; g < 2; g++)
            boff[g] = (uint32_t)((warp_n * 32 + g * 16 + rB) * ROWB + ksB * 16);
    }

    const int spt = K / BKE;
    const int total = nterms * spt;

    auto load_stage = [&](const __half* Wp, int k0, int bufidx) {
        uint32_t dA = sbase + (uint32_t)bufidx * 2u * STAGE;
        uint32_t dB = dA + STAGE;
#pragma unroll
        for (int i = 0; i < 4; i++) {
            int c = i * 256 + tid;
            int r = c >> 3, seg = c & 7;
            uint32_t o = (uint32_t)(r * ROWB + seg * 16);
            cp16(dA + o, A  + (size_t)(bm + r) * K + k0 + seg * 8);
            cp16(dB + o, Wp + (size_t)(bn + r) * K + k0 + seg * 8);
        }
    };

    load_stage(Whi, 0, 0);
    cp_commit();

    for (int s = 0; s < total; s++) {
        const int buf = s & 1;
        if (s + 1 < total) {
            const int s1 = s + 1;
            const __half* Wp = (s1 / spt == 1) ? Wlo : Whi;
            load_stage(Wp, (s1 % spt) * BKE, buf ^ 1);
            cp_commit();
            cp_wait<1>();
        } else {
            cp_wait<0>();
        }
        __syncthreads();

        const uint32_t sA = sbase + (uint32_t)buf * 2u * STAGE;
        const uint32_t sB = sA + STAGE;
#pragma unroll
        for (int ks = 0; ks < 4; ks++) {
            uint32_t br[8];
            ldm4(br,     sB + boff[0] + ks * 32);
            ldm4(br + 4, sB + boff[1] + ks * 32);
#pragma unroll
            for (int mf = 0; mf < 4; mf++) {
                uint32_t ar[4];
                ldm4(ar, sA + aoff[mf] + ks * 32);
#pragma unroll
                for (int nf = 0; nf < 4; nf++)
                    mma16816(acc[mf][nf], ar, br + nf * 2);
            }
        }
        __syncthreads();
    }

    // ------------- fused epilogue -------------
    float2 bv[4];
#pragma unroll
    for (int nf = 0; nf < 4; nf++)
        bv[nf] = *(const float2*)&bias[bn + warp_n * 32 + nf * 8 + (lane & 3) * 2];

#pragma unroll
    for (int mf = 0; mf < 4; mf++) {
#pragma unroll
        for (int h = 0; h < 2; h++) {
            const int row = bm + warp_m * 64 + mf * 16 + (lane >> 2) + h * 8;
#pragma unroll
            for (int nf = 0; nf < 4; nf++) {
                const int col = bn + warp_n * 32 + nf * 8 + (lane & 3) * 2;
                const size_t off = (size_t)row * N + col;
                float v0 = acc[mf][nf][h * 2 + 0] + bv[nf].x;
                float v1 = acc[mf][nf][h * 2 + 1] + bv[nf].y;
                if (mode & F_GATE) {
                    __half2 g = *(const __half2*)&aux[off];
                    v0 *= sigm(__half2float(g.x));
                    v1 *= sigm(__half2float(g.y));
                } else if (mode & F_SILU) {
                    v0 *= sigm(v0); v1 *= sigm(v1);
                }
                if (mode & F_OUT16) {
                    __half2 o; o.x = __float2half(v0); o.y = __float2half(v1);
                    *(__half2*)&Ch[off] = o;
                } else {
                    *(float2*)&Cf[off] = make_float2(v0, v1);
                }
            }
        }
    }
}

// ---------------- conversion / split kernels ----------------------------------
__global__ void cvt_f16(const float* __restrict__ in, __half* __restrict__ o, int n)
{
    int i = (blockIdx.x * blockDim.x + threadIdx.x) * 4;
    if (i < n) {
        float4 v = *(const float4*)&in[i];
        __half2 a; a.x = __float2half(v.x); a.y = __float2half(v.y);
        __half2 b; b.x = __float2half(v.z); b.y = __float2half(v.w);
        *(__half2*)&o[i]     = a;
        *(__half2*)&o[i + 2] = b;
    }
}

__global__ void split_f16(const float* __restrict__ in,
                          __half* __restrict__ hi, __half* __restrict__ lo, int n)
{
    int i = (blockIdx.x * blockDim.x + threadIdx.x) * 4;
    if (i < n) {
        float4 v = *(const float4*)&in[i];
        float vv[4] = {v.x, v.y, v.z, v.w};
        __half hh[4], ll[4];
#pragma unroll
        for (int q = 0; q < 4; q++) {
            hh[q] = __float2half(vv[q]);
            ll[q] = __float2half(vv[q] - __half2float(hh[q]));
        }
        *(__half2*)&hi[i]     = __halves2half2(hh[0], hh[1]);
        *(__half2*)&hi[i + 2] = __halves2half2(hh[2], hh[3]);
        *(__half2*)&lo[i]     = __halves2half2(ll[0], ll[1]);
        *(__half2*)&lo[i + 2] = __halves2half2(ll[2], ll[3]);
    }
}

// ---------------- rotated-frame relu scan (validated) -------------------------
__global__ void scan_pass1(const float* __restrict__ B,
                           float* __restrict__ Ac, float* __restrict__ Bc)
{
    int t    = blockIdx.x * blockDim.x + threadIdx.x;
    int lane = t & (HIDN - 1);
    int chnk = t >> 12;
    float Aa = -1e30f, Ss = 0.f;
    int base = chnk * CHUNK;
#pragma unroll 8
    for (int i = 0; i < CHUNK; i++) {
        int row = base + i;
        float b = B[(size_t)row * HIDN + ((lane + row) & (HIDN - 1))];
        Aa = fmaxf(0.f, b + Aa);
        Ss += b;
    }
    Ac[t] = Aa; Bc[t] = Ss;
}

__global__ void scan_combine(const float* __restrict__ hidden,
                             const float* __restrict__ Ac, const float* __restrict__ Bc,
                             float* __restrict__ Gb)
{
    int lane = blockIdx.x * blockDim.x + threadIdx.x;
    float gv = hidden[(lane - 1) & (HIDN - 1)];
    Gb[lane] = gv;
    for (int c = 0; c < NCHUNK; c++) {
        gv = fmaxf(Ac[c * HIDN + lane], Bc[c * HIDN + lane] + gv);
        Gb[(c + 1) * HIDN + lane] = gv;
    }
}

__global__ void scan_pass2(const float* __restrict__ B, const float* __restrict__ Gb,
                           float* __restrict__ out, float* __restrict__ hlast, int write_h)
{
    int t    = blockIdx.x * blockDim.x + threadIdx.x;
    int lane = t & (HIDN - 1);
    int chnk = t >> 12;
    float gv = Gb[chnk * HIDN + lane];
    int base = chnk * CHUNK;
#pragma unroll 4
    for (int i = 0; i < CHUNK; i++) {
        int row = base + i;
        int col = (lane + row) & (HIDN - 1);
        gv = fmaxf(0.f, B[(size_t)row * HIDN + col] + gv);
        out[(size_t)row * HIDN + col] = gv;
    }
    if (write_h && chnk == NCHUNK - 1)
        hlast[(lane - 1) & (HIDN - 1)] = gv;
}

// ---------------- launch ------------------------------------------------------
extern "C" void kernel_launch(void* const* d_in, const int* in_sizes, int n_in,
                              void* d_out, int out_size)
{
    const float* x      = (const float*)d_in[0];
    const float* hidden = (const float*)d_in[1];
    const float* w_in   = (const float*)d_in[2];
    const float* b_in   = (const float*)d_in[3];
    const float* wg0    = (const float*)d_in[4];
    const float* bg0    = (const float*)d_in[5];
    const float* wg0g   = (const float*)d_in[6];
    const float* bg0g   = (const float*)d_in[7];
    const float* wg_sh  = (const float*)d_in[8];
    const float* bg_sh  = (const float*)d_in[9];
    const float* w_h    = (const float*)d_in[10];
    const float* b_h    = (const float*)d_in[11];
    const float* w2     = (const float*)d_in[12];
    const float* b2     = (const float*)d_in[13];

    float* out   = (float*)d_out;
    float* hlast = out + (size_t)SEQ * HIDN;
    int write_h  = (out_size >= SEQ * HIDN + HIDN) ? 1 : 0;

    cudaFuncSetAttribute(gemm_f16, cudaFuncAttributeMaxDynamicSharedMemorySize, SMEM_DYN);

    __half *xh, *h1h, *h2h, *h3h, *t2h, *Gh;
    __half *winhi, *winlo, *wg0h, *wgGh, *wshh, *whh, *w2h;
    float *B, *Ac, *Bc, *Gb;
    cudaGetSymbolAddress((void**)&xh,  g_xh);
    cudaGetSymbolAddress((void**)&h1h, g_h1h);
    cudaGetSymbolAddress((void**)&h2h, g_h2h);
    cudaGetSymbolAddress((void**)&h3h, g_h3h);
    cudaGetSymbolAddress((void**)&t2h, g_t2h);
    cudaGetSymbolAddress((void**)&Gh,  g_Gh);
    cudaGetSymbolAddress((void**)&winhi, g_winhi); cudaGetSymbolAddress((void**)&winlo, g_winlo);
    cudaGetSymbolAddress((void**)&wg0h, g_wg0h);
    cudaGetSymbolAddress((void**)&wgGh, g_wgGh);
    cudaGetSymbolAddress((void**)&wshh, g_wshh);
    cudaGetSymbolAddress((void**)&whh,  g_whh);
    cudaGetSymbolAddress((void**)&w2h,  g_w2h);
    cudaGetSymbolAddress((void**)&B,  g_B);
    cudaGetSymbolAddress((void**)&Ac, g_Ac);
    cudaGetSymbolAddress((void**)&Bc, g_Bc);
    cudaGetSymbolAddress((void**)&Gb, g_Gb);

    // conversions
    cvt_f16  <<<(SEQ*INP/4  + 255)/256, 256>>>(x,     xh,  SEQ*INP);
    split_f16<<<(HYP*INP/4  + 255)/256, 256>>>(w_in,  winhi, winlo, HYP*INP);
    cvt_f16  <<<(HYP*HYP/4  + 255)/256, 256>>>(wg0,   wg0h, HYP*HYP);
    cvt_f16  <<<(HYP*HYP/4  + 255)/256, 256>>>(wg0g,  wgGh, HYP*HYP);
    cvt_f16  <<<(HYP*HYP/4  + 255)/256, 256>>>(wg_sh, wshh, HYP*HYP);
    cvt_f16  <<<(HIDN*HYP/4 + 255)/256, 256>>>(w_h,   whh,  HIDN*HYP);
    cvt_f16  <<<(HIDN*INP/4 + 255)/256, 256>>>(w2,    w2h,  HIDN*INP);

    const dim3 gHyp(HYP / BN, SEQ / BM);    // 8 x 64
    const dim3 gHid(HIDN / BN, SEQ / BM);   // 32 x 64

    // h1 = x @ w_in^T + b_in                      (2 terms -> f16)
    gemm_f16<<<gHyp, 256, SMEM_DYN>>>(xh, winhi, winlo, b_in, nullptr,
                                      HYP, INP, 2, F_OUT16, nullptr, h1h);
    // t2 = h1 @ wg0g^T + bg0g                     (1 term gate -> f16)
    gemm_f16<<<gHyp, 256, SMEM_DYN>>>(h1h, wgGh, nullptr, bg0g, nullptr,
                                      HYP, HYP, 1, F_OUT16, nullptr, t2h);
    // h2 = (h1 @ wg0^T + bg0) * sigmoid(t2)       (1 term -> f16)
    gemm_f16<<<gHyp, 256, SMEM_DYN>>>(h1h, wg0h, nullptr, bg0, t2h,
                                      HYP, HYP, 1, F_OUT16 | F_GATE, nullptr, h2h);
    // h3 = silu(h2 @ wg_sh^T + bg_sh)             (1 term -> f16)
    gemm_f16<<<gHyp, 256, SMEM_DYN>>>(h2h, wshh, nullptr, bg_sh, nullptr,
                                      HYP, HYP, 1, F_OUT16 | F_SILU, nullptr, h3h);
    // G = x @ w2^T + b2                           (1 term gate -> f16)
    gemm_f16<<<gHid, 256, SMEM_DYN>>>(xh, w2h, nullptr, b2, nullptr,
                                      HIDN, INP, 1, F_OUT16, nullptr, Gh);
    // B = (h3 @ w_h^T + b_h) * sigmoid(G)         (1 term -> f32)
    gemm_f16<<<gHid, 256, SMEM_DYN>>>(h3h, whh, nullptr, b_h, Gh,
                                      HIDN, HYP, 1, F_GATE, B, nullptr);

    // chunked rotated-frame scan
    scan_pass1 <<<NCHUNK*HIDN/256, 256>>>(B, Ac, Bc);
    scan_combine<<<HIDN/256, 256>>>(hidden, Ac, Bc, Gb);
    scan_pass2 <<<NCHUNK*HIDN/256, 256>>>(B, Gb, out, hlast, write_h);
}

// round 7
// speedup vs baseline: 6.4316x; 1.2480x over previous
#include <cuda_runtime.h>
#include <cuda_fp16.h>
#include <stdint.h>
#include <math.h>

#define SEQ   8192
#define INP   512
#define HYP   1024
#define HIDN  4096
#define CHUNK 128
#define NCHUNK (SEQ/CHUNK)   // 64

// ---------------- scratch (static __device__, no allocations) ----------------
__device__ __half g_xh  [SEQ*INP];
__device__ __half g_h1h [SEQ*HYP];
__device__ __half g_h2h [SEQ*HYP];
__device__ __half g_h3h [SEQ*HYP];
__device__ __half g_Gh  [SEQ*HIDN];
__device__ __half g_Bh  [SEQ*HIDN];          // gated pre-recurrence values (fp16)
__device__ __half g_winh[HYP*INP];
__device__ __half g_wI  [2*HYP*HYP];         // interleaved wg0/wg0g
__device__ __half g_wshh[HYP*HYP];
__device__ __half g_whh [HIDN*HYP];
__device__ __half g_w2h [HIDN*INP];
__device__ float  g_biasI[2*HYP];            // interleaved bg0/bg0g
__device__ float g_Ac[NCHUNK*HIDN];
__device__ float g_Bc[NCHUNK*HIDN];
__device__ float g_Gb[(NCHUNK+1)*HIDN];

// ---------------- PTX helpers (sm_100-portable only) --------------------------
__device__ __forceinline__ uint32_t smem_u32(const void* p) {
    uint32_t a;
    asm("{ .reg .u64 t; cvta.to.shared.u64 t, %1; cvt.u32.u64 %0, t; }" : "=r"(a) : "l"(p));
    return a;
}
__device__ __forceinline__ void cp16(uint32_t dst, const void* src) {
    asm volatile("cp.async.cg.shared.global [%0], [%1], 16;" :: "r"(dst), "l"(src));
}
__device__ __forceinline__ void cp_commit() { asm volatile("cp.async.commit_group;"); }
template <int N> __device__ __forceinline__ void cp_wait() {
    asm volatile("cp.async.wait_group %0;" :: "n"(N));
}
__device__ __forceinline__ void ldm4(uint32_t* r, uint32_t addr) {
    asm volatile("ldmatrix.sync.aligned.m8n8.x4.shared.b16 {%0,%1,%2,%3}, [%4];"
                 : "=r"(r[0]), "=r"(r[1]), "=r"(r[2]), "=r"(r[3]) : "r"(addr));
}
__device__ __forceinline__ void mma16816(float* d, const uint32_t* a, const uint32_t* b) {
    asm volatile(
        "mma.sync.aligned.m16n8k16.row.col.f32.f16.f16.f32 "
        "{%0,%1,%2,%3}, {%4,%5,%6,%7}, {%8,%9}, {%0,%1,%2,%3};"
        : "+f"(d[0]), "+f"(d[1]), "+f"(d[2]), "+f"(d[3])
        : "r"(a[0]), "r"(a[1]), "r"(a[2]), "r"(a[3]), "r"(b[0]), "r"(b[1]));
}

// ---------------- fp16 GEMM: C[M,N] = A[M,K] @ W[N,K]^T + bias ----------------
// 128x128 tile, BK=64, XOR-swizzled 128B smem rows, 3-stage cp.async ring,
// one __syncthreads per stage, 8 warps (2x4), 64x32 warp tiles.
#define BM 128
#define BN 128
#define BKE 64
#define OPER 16384               // 128 rows * 128 B per operand
#define STAGE (2*OPER)           // 32 KB
#define NSTAGE 3
#define SMEM_DYN (NSTAGE*STAGE)  // 98304 B

#define M_PLAIN 0
#define M_GATE  1
#define M_SILU  2
#define M_PAIR  3   // interleaved value/gate columns -> v*sigm(g), Nout = N/2

__device__ __forceinline__ float sigm(float x) { return 1.f / (1.f + expf(-x)); }

__global__ __launch_bounds__(256, 2)
void gemm_f16(const __half* __restrict__ A, const __half* __restrict__ W,
              const float* __restrict__ bias, const __half* __restrict__ aux,
              int N, int K, int Nout, int mode, __half* __restrict__ Ch)
{
    extern __shared__ char dsmem[];
    const int tid = threadIdx.x, lane = tid & 31, wid = tid >> 5;
    const int warp_m = wid >> 2, warp_n = wid & 3;
    const int bm = blockIdx.y * BM, bn = blockIdx.x * BN;
    const uint32_t sbase = smem_u32(dsmem);

    float acc[4][4][4];
#pragma unroll
    for (int i = 0; i < 4; i++)
#pragma unroll
        for (int j = 0; j < 4; j++)
#pragma unroll
            for (int q = 0; q < 4; q++) acc[i][j][q] = 0.f;

    // per-lane ldmatrix row bases (swizzle applied per ks below)
    uint32_t arow[4], asw[4], brow[2], bsw[2];
    const int ksA = (lane >> 4) & 1;
    const int ksB = (lane >> 3) & 1;
    {
        int rA = (lane & 7) + ((lane >> 3) & 1) * 8;
#pragma unroll
        for (int mf = 0; mf < 4; mf++) {
            int r = warp_m * 64 + mf * 16 + rA;
            arow[mf] = (uint32_t)(r * 128);
            asw[mf]  = (uint32_t)(r & 7);
        }
        int rB = (lane & 7) + ((lane >> 4) & 1) * 8;
#pragma unroll
        for (int g = 0; g < 2; g++) {
            int r = warp_n * 32 + g * 16 + rB;
            brow[g] = (uint32_t)(r * 128);
            bsw[g]  = (uint32_t)(r & 7);
        }
    }

    const int spt = K / BKE;

    auto load_stage = [&](int k0, int buf) {
        uint32_t dA = sbase + (uint32_t)buf * STAGE;
        uint32_t dB = dA + OPER;
#pragma unroll
        for (int i = 0; i < 4; i++) {
            int c = i * 256 + tid;            // 0..1023
            int r = c >> 3, seg = c & 7;
            uint32_t o = (uint32_t)(r * 128 + ((seg ^ (r & 7)) << 4));
            cp16(dA + o, A + (size_t)(bm + r) * K + k0 + seg * 8);
            cp16(dB + o, W + (size_t)(bn + r) * K + k0 + seg * 8);
        }
    };

    // prologue: 2 stages in flight
    load_stage(0, 0);  cp_commit();
    load_stage(BKE, 1); cp_commit();

    for (int s = 0; s < spt; s++) {
        const int buf = s % NSTAGE;
        if (s < spt - 1) cp_wait<1>(); else cp_wait<0>();
        __syncthreads();
        if (s + 2 < spt) { load_stage((s + 2) * BKE, (s + 2) % NSTAGE); cp_commit(); }

        const uint32_t sA = sbase + (uint32_t)buf * STAGE;
        const uint32_t sB = sA + OPER;
#pragma unroll
        for (int ks = 0; ks < 4; ks++) {
            uint32_t br[8];
            ldm4(br,     sB + brow[0] + (((uint32_t)(ks * 2) + ksB) ^ bsw[0]) * 16);
            ldm4(br + 4, sB + brow[1] + (((uint32_t)(ks * 2) + ksB) ^ bsw[1]) * 16);
#pragma unroll
            for (int mf = 0; mf < 4; mf++) {
                uint32_t ar[4];
                ldm4(ar, sA + arow[mf] + (((uint32_t)(ks * 2) + ksA) ^ asw[mf]) * 16);
#pragma unroll
                for (int nf = 0; nf < 4; nf++)
                    mma16816(acc[mf][nf], ar, br + nf * 2);
            }
        }
    }

    // ------------- fused epilogue -------------
    float2 bv[4];
#pragma unroll
    for (int nf = 0; nf < 4; nf++)
        bv[nf] = *(const float2*)&bias[bn + warp_n * 32 + nf * 8 + (lane & 3) * 2];

#pragma unroll
    for (int mf = 0; mf < 4; mf++) {
#pragma unroll
        for (int h = 0; h < 2; h++) {
            const int row = bm + warp_m * 64 + mf * 16 + (lane >> 2) + h * 8;
#pragma unroll
            for (int nf = 0; nf < 4; nf++) {
                const int col = bn + warp_n * 32 + nf * 8 + (lane & 3) * 2;
                float v0 = acc[mf][nf][h * 2 + 0] + bv[nf].x;
                float v1 = acc[mf][nf][h * 2 + 1] + bv[nf].y;
                if (mode == M_PAIR) {
                    // v0 = value, v1 = its gate (interleaved weights)
                    Ch[(size_t)row * Nout + (col >> 1)] = __float2half(v0 * sigm(v1));
                } else {
                    if (mode == M_GATE) {
                        __half2 g = *(const __half2*)&aux[(size_t)row * N + col];
                        v0 *= sigm(__half2float(g.x));
                        v1 *= sigm(__half2float(g.y));
                    } else if (mode == M_SILU) {
                        v0 *= sigm(v0); v1 *= sigm(v1);
                    }
                    __half2 o; o.x = __float2half(v0); o.y = __float2half(v1);
                    *(__half2*)&Ch[(size_t)row * Nout + col] = o;
                }
            }
        }
    }
}

// ---------------- conversion kernels ------------------------------------------
__global__ void cvt_f16(const float* __restrict__ in, __half* __restrict__ o, int n)
{
    int i = (blockIdx.x * blockDim.x + threadIdx.x) * 4;
    if (i < n) {
        float4 v = *(const float4*)&in[i];
        __half2 a; a.x = __float2half(v.x); a.y = __float2half(v.y);
        __half2 b; b.x = __float2half(v.z); b.y = __float2half(v.w);
        *(__half2*)&o[i]     = a;
        *(__half2*)&o[i + 2] = b;
    }
}

// interleave rows: o[2i] = a[i], o[2i+1] = b[i]  (rows of length K)
__global__ void interleave_w(const float* __restrict__ a, const float* __restrict__ b,
                             __half* __restrict__ o, int K, int n)
{
    int i = (blockIdx.x * blockDim.x + threadIdx.x) * 4;
    if (i < n) {
        int r = i / K, k = i - r * K;
        const float* s = (r & 1) ? b : a;
        float4 v = *(const float4*)&s[(size_t)(r >> 1) * K + k];
        __half2 p; p.x = __float2half(v.x); p.y = __float2half(v.y);
        __half2 q; q.x = __float2half(v.z); q.y = __float2half(v.w);
        *(__half2*)&o[i]     = p;
        *(__half2*)&o[i + 2] = q;
    }
}

__global__ void interleave_bias(const float* __restrict__ a, const float* __restrict__ b,
                                float* __restrict__ o, int n)
{
    int i = blockIdx.x * blockDim.x + threadIdx.x;
    if (i < n) { o[2 * i] = a[i]; o[2 * i + 1] = b[i]; }
}

// ---------------- rotated-frame relu scan (fp16 B) ----------------------------
__global__ void scan_pass1(const __half* __restrict__ B,
                           float* __restrict__ Ac, float* __restrict__ Bc)
{
    int t    = blockIdx.x * blockDim.x + threadIdx.x;
    int lane = t & (HIDN - 1);
    int chnk = t >> 12;
    float Aa = -1e30f, Ss = 0.f;
    int base = chnk * CHUNK;
#pragma unroll 8
    for (int i = 0; i < CHUNK; i++) {
        int row = base + i;
        float b = __half2float(B[(size_t)row * HIDN + ((lane + row) & (HIDN - 1))]);
        Aa = fmaxf(0.f, b + Aa);
        Ss += b;
    }
    Ac[t] = Aa; Bc[t] = Ss;
}

__global__ void scan_combine(const float* __restrict__ hidden,
                             const float* __restrict__ Ac, const float* __restrict__ Bc,
                             float* __restrict__ Gb)
{
    int lane = blockIdx.x * blockDim.x + threadIdx.x;
    float gv = hidden[(lane - 1) & (HIDN - 1)];
    Gb[lane] = gv;
    for (int c = 0; c < NCHUNK; c++) {
        gv = fmaxf(Ac[c * HIDN + lane], Bc[c * HIDN + lane] + gv);
        Gb[(c + 1) * HIDN + lane] = gv;
    }
}

__global__ void scan_pass2(const __half* __restrict__ B, const float* __restrict__ Gb,
                           float* __restrict__ out, float* __restrict__ hlast, int write_h)
{
    int t    = blockIdx.x * blockDim.x + threadIdx.x;
    int lane = t & (HIDN - 1);
    int chnk = t >> 12;
    float gv = Gb[chnk * HIDN + lane];
    int base = chnk * CHUNK;
#pragma unroll 4
    for (int i = 0; i < CHUNK; i++) {
        int row = base + i;
        int col = (lane + row) & (HIDN - 1);
        gv = fmaxf(0.f, __half2float(B[(size_t)row * HIDN + col]) + gv);
        out[(size_t)row * HIDN + col] = gv;
    }
    if (write_h && chnk == NCHUNK - 1)
        hlast[(lane - 1) & (HIDN - 1)] = gv;
}

// ---------------- launch ------------------------------------------------------
extern "C" void kernel_launch(void* const* d_in, const int* in_sizes, int n_in,
                              void* d_out, int out_size)
{
    const float* x      = (const float*)d_in[0];
    const float* hidden = (const float*)d_in[1];
    const float* w_in   = (const float*)d_in[2];
    const float* b_in   = (const float*)d_in[3];
    const float* wg0    = (const float*)d_in[4];
    const float* bg0    = (const float*)d_in[5];
    const float* wg0g   = (const float*)d_in[6];
    const float* bg0g   = (const float*)d_in[7];
    const float* wg_sh  = (const float*)d_in[8];
    const float* bg_sh  = (const float*)d_in[9];
    const float* w_h    = (const float*)d_in[10];
    const float* b_h    = (const float*)d_in[11];
    const float* w2     = (const float*)d_in[12];
    const float* b2     = (const float*)d_in[13];

    float* out   = (float*)d_out;
    float* hlast = out + (size_t)SEQ * HIDN;
    int write_h  = (out_size >= SEQ * HIDN + HIDN) ? 1 : 0;

    cudaFuncSetAttribute(gemm_f16, cudaFuncAttributeMaxDynamicSharedMemorySize, SMEM_DYN);

    __half *xh, *h1h, *h2h, *h3h, *Gh, *Bh, *winh, *wI, *wshh, *whh, *w2h;
    float *biasI, *Ac, *Bc, *Gb;
    cudaGetSymbolAddress((void**)&xh,  g_xh);
    cudaGetSymbolAddress((void**)&h1h, g_h1h);
    cudaGetSymbolAddress((void**)&h2h, g_h2h);
    cudaGetSymbolAddress((void**)&h3h, g_h3h);
    cudaGetSymbolAddress((void**)&Gh,  g_Gh);
    cudaGetSymbolAddress((void**)&Bh,  g_Bh);
    cudaGetSymbolAddress((void**)&winh, g_winh);
    cudaGetSymbolAddress((void**)&wI,   g_wI);
    cudaGetSymbolAddress((void**)&wshh, g_wshh);
    cudaGetSymbolAddress((void**)&whh,  g_whh);
    cudaGetSymbolAddress((void**)&w2h,  g_w2h);
    cudaGetSymbolAddress((void**)&biasI, g_biasI);
    cudaGetSymbolAddress((void**)&Ac, g_Ac);
    cudaGetSymbolAddress((void**)&Bc, g_Bc);
    cudaGetSymbolAddress((void**)&Gb, g_Gb);

    // conversions
    cvt_f16<<<(SEQ*INP/4  + 255)/256, 256>>>(x,     xh,   SEQ*INP);
    cvt_f16<<<(HYP*INP/4  + 255)/256, 256>>>(w_in,  winh, HYP*INP);
    interleave_w<<<(2*HYP*HYP/4 + 255)/256, 256>>>(wg0, wg0g, wI, HYP, 2*HYP*HYP);
    interleave_bias<<<(HYP + 255)/256, 256>>>(bg0, bg0g, biasI, HYP);
    cvt_f16<<<(HYP*HYP/4  + 255)/256, 256>>>(wg_sh, wshh, HYP*HYP);
    cvt_f16<<<(HIDN*HYP/4 + 255)/256, 256>>>(w_h,   whh,  HIDN*HYP);
    cvt_f16<<<(HIDN*INP/4 + 255)/256, 256>>>(w2,    w2h,  HIDN*INP);

    const dim3 gHyp (HYP  / BN,    SEQ / BM);   //  8 x 64
    const dim3 gPair(2*HYP / BN,   SEQ / BM);   // 16 x 64
    const dim3 gHid (HIDN / BN,    SEQ / BM);   // 32 x 64

    // h1 = x @ w_in^T + b_in
    gemm_f16<<<gHyp, 256, SMEM_DYN>>>(xh, winh, b_in, nullptr,
                                      HYP, INP, HYP, M_PLAIN, h1h);
    // h2 = (h1 @ wg0^T + bg0) * sigmoid(h1 @ wg0g^T + bg0g)   [fused, interleaved]
    gemm_f16<<<gPair, 256, SMEM_DYN>>>(h1h, wI, biasI, nullptr,
                                       2*HYP, HYP, HYP, M_PAIR, h2h);
    // h3 = silu(h2 @ wg_sh^T + bg_sh)
    gemm_f16<<<gHyp, 256, SMEM_DYN>>>(h2h, wshh, bg_sh, nullptr,
                                      HYP, HYP, HYP, M_SILU, h3h);
    // G = x @ w2^T + b2
    gemm_f16<<<gHid, 256, SMEM_DYN>>>(xh, w2h, b2, nullptr,
                                      HIDN, INP, HIDN, M_PLAIN, Gh);
    // B = (h3 @ w_h^T + b_h) * sigmoid(G)
    gemm_f16<<<gHid, 256, SMEM_DYN>>>(h3h, whh, b_h, Gh,
                                      HIDN, HYP, HIDN, M_GATE, Bh);

    // chunked rotated-frame scan
    scan_pass1 <<<NCHUNK*HIDN/256, 256>>>(Bh, Ac, Bc);
    scan_combine<<<HIDN/256, 256>>>(hidden, Ac, Bc, Gb);
    scan_pass2 <<<NCHUNK*HIDN/256, 256>>>(Bh, Gb, out, hlast, write_h);
}

// round 8
// speedup vs baseline: 6.5356x; 1.0162x over previous
#include <cuda_runtime.h>
#include <cuda_fp16.h>
#include <stdint.h>
#include <math.h>

#define SEQ   8192
#define INP   512
#define HYP   1024
#define HIDN  4096
#define CHUNK 128
#define NCHUNK (SEQ/CHUNK)   // 64

// ---------------- scratch (static __device__, no allocations) ----------------
__device__ __half g_xh  [SEQ*INP];
__device__ __half g_h1h [SEQ*HYP];
__device__ __half g_h2h [SEQ*HYP];
__device__ __half g_h3h [SEQ*HYP];
__device__ __half g_Gh  [SEQ*HIDN];
__device__ __half g_Bh  [SEQ*HIDN];
__device__ __half g_w15 [(HYP+HIDN)*INP];    // [w_in ; w2] rows, K=512
__device__ __half g_wI  [2*HYP*HYP];         // interleaved wg0/wg0g
__device__ __half g_wshh[HYP*HYP];
__device__ __half g_whh [HIDN*HYP];
__device__ float g_Ac[NCHUNK*HIDN];
__device__ float g_Bc[NCHUNK*HIDN];
__device__ float g_Gb[(NCHUNK+1)*HIDN];

// ---------------- PTX helpers (sm_100-portable only) --------------------------
__device__ __forceinline__ uint32_t smem_u32(const void* p) {
    uint32_t a;
    asm("{ .reg .u64 t; cvta.to.shared.u64 t, %1; cvt.u32.u64 %0, t; }" : "=r"(a) : "l"(p));
    return a;
}
__device__ __forceinline__ void cp16(uint32_t dst, const void* src) {
    asm volatile("cp.async.cg.shared.global [%0], [%1], 16;" :: "r"(dst), "l"(src));
}
__device__ __forceinline__ void cp_commit() { asm volatile("cp.async.commit_group;"); }
template <int N> __device__ __forceinline__ void cp_wait() {
    asm volatile("cp.async.wait_group %0;" :: "n"(N));
}
__device__ __forceinline__ void ldm4(uint32_t* r, uint32_t addr) {
    asm volatile("ldmatrix.sync.aligned.m8n8.x4.shared.b16 {%0,%1,%2,%3}, [%4];"
                 : "=r"(r[0]), "=r"(r[1]), "=r"(r[2]), "=r"(r[3]) : "r"(addr));
}
__device__ __forceinline__ void mma16816(float* d, const uint32_t* a, const uint32_t* b) {
    asm volatile(
        "mma.sync.aligned.m16n8k16.row.col.f32.f16.f16.f32 "
        "{%0,%1,%2,%3}, {%4,%5,%6,%7}, {%8,%9}, {%0,%1,%2,%3};"
        : "+f"(d[0]), "+f"(d[1]), "+f"(d[2]), "+f"(d[3])
        : "r"(a[0]), "r"(a[1]), "r"(a[2]), "r"(a[3]), "r"(b[0]), "r"(b[1]));
}

// ---------------- fp16 GEMM: C[M,N] = A[M,K] @ W[N,K]^T + bias ----------------
// 128x128 tile, BK=64, XOR-swizzled 128B smem rows, 3-stage cp.async ring.
#define BM 128
#define BN 128
#define BKE 64
#define OPER 16384
#define STAGE (2*OPER)           // 32 KB
#define NSTAGE 3
#define SMEM_DYN (NSTAGE*STAGE)  // 98304 B

#define M_PLAIN 0
#define M_GATE  1
#define M_SILU  2
#define M_PAIR  3   // interleaved value/gate cols -> v*sigm(g); bias/bias2 = bg0/bg0g
#define M_DUAL  4   // bn<HYP -> Ch(+bias, N=HYP); else -> Ch2(+bias2, N=HIDN)

__device__ __forceinline__ float sigm(float x) { return 1.f / (1.f + expf(-x)); }

__global__ __launch_bounds__(256, 2)
void gemm_f16(const __half* __restrict__ A, const __half* __restrict__ W,
              const float* __restrict__ bias, const float* __restrict__ bias2,
              const __half* __restrict__ aux,
              int N, int K, int Nout, int mode,
              __half* __restrict__ Ch, __half* __restrict__ Ch2)
{
    extern __shared__ char dsmem[];
    const int tid = threadIdx.x, lane = tid & 31, wid = tid >> 5;
    const int warp_m = wid >> 2, warp_n = wid & 3;
    const int bm = blockIdx.y * BM, bn = blockIdx.x * BN;
    const uint32_t sbase = smem_u32(dsmem);

    float acc[4][4][4];
#pragma unroll
    for (int i = 0; i < 4; i++)
#pragma unroll
        for (int j = 0; j < 4; j++)
#pragma unroll
            for (int q = 0; q < 4; q++) acc[i][j][q] = 0.f;

    uint32_t arow[4], asw[4], brow[2], bsw[2];
    const int ksA = (lane >> 4) & 1;
    const int ksB = (lane >> 3) & 1;
    {
        int rA = (lane & 7) + ((lane >> 3) & 1) * 8;
#pragma unroll
        for (int mf = 0; mf < 4; mf++) {
            int r = warp_m * 64 + mf * 16 + rA;
            arow[mf] = (uint32_t)(r * 128);
            asw[mf]  = (uint32_t)(r & 7);
        }
        int rB = (lane & 7) + ((lane >> 4) & 1) * 8;
#pragma unroll
        for (int g = 0; g < 2; g++) {
            int r = warp_n * 32 + g * 16 + rB;
            brow[g] = (uint32_t)(r * 128);
            bsw[g]  = (uint32_t)(r & 7);
        }
    }

    const int spt = K / BKE;

    auto load_stage = [&](int k0, int buf) {
        uint32_t dA = sbase + (uint32_t)buf * STAGE;
        uint32_t dB = dA + OPER;
#pragma unroll
        for (int i = 0; i < 4; i++) {
            int c = i * 256 + tid;
            int r = c >> 3, seg = c & 7;
            uint32_t o = (uint32_t)(r * 128 + ((seg ^ (r & 7)) << 4));
            cp16(dA + o, A + (size_t)(bm + r) * K + k0 + seg * 8);
            cp16(dB + o, W + (size_t)(bn + r) * K + k0 + seg * 8);
        }
    };

    load_stage(0, 0);  cp_commit();
    load_stage(BKE, 1); cp_commit();

    for (int s = 0; s < spt; s++) {
        const int buf = s % NSTAGE;
        if (s < spt - 1) cp_wait<1>(); else cp_wait<0>();
        __syncthreads();
        if (s + 2 < spt) { load_stage((s + 2) * BKE, (s + 2) % NSTAGE); cp_commit(); }

        const uint32_t sA = sbase + (uint32_t)buf * STAGE;
        const uint32_t sB = sA + OPER;
#pragma unroll
        for (int ks = 0; ks < 4; ks++) {
            uint32_t br[8];
            ldm4(br,     sB + brow[0] + (((uint32_t)(ks * 2) + ksB) ^ bsw[0]) * 16);
            ldm4(br + 4, sB + brow[1] + (((uint32_t)(ks * 2) + ksB) ^ bsw[1]) * 16);
#pragma unroll
            for (int mf = 0; mf < 4; mf++) {
                uint32_t ar[4];
                ldm4(ar, sA + arow[mf] + (((uint32_t)(ks * 2) + ksA) ^ asw[mf]) * 16);
#pragma unroll
                for (int nf = 0; nf < 4; nf++)
                    mma16816(acc[mf][nf], ar, br + nf * 2);
            }
        }
    }

    // ------------- fused epilogue -------------
    // Region routing (M_DUAL): first HYP cols -> Ch/bias, rest -> Ch2/bias2.
    __half* outp = Ch;
    const float* biasp = bias;
    int Nloc = Nout, nbase = bn;
    if (mode == M_DUAL && bn >= HYP) {
        outp = Ch2; biasp = bias2; Nloc = HIDN; nbase = bn - HYP;
    }

    float2 bv[4];
#pragma unroll
    for (int nf = 0; nf < 4; nf++) {
        int nloc = nbase + warp_n * 32 + nf * 8 + (lane & 3) * 2;
        if (mode == M_PAIR) {   // even col = value (bias), odd = gate (bias2)
            bv[nf].x = bias[nloc >> 1];
            bv[nf].y = bias2[nloc >> 1];
        } else {
            bv[nf] = *(const float2*)&biasp[nloc];
        }
    }

#pragma unroll
    for (int mf = 0; mf < 4; mf++) {
#pragma unroll
        for (int h = 0; h < 2; h++) {
            const int row = bm + warp_m * 64 + mf * 16 + (lane >> 2) + h * 8;
#pragma unroll
            for (int nf = 0; nf < 4; nf++) {
                const int nloc = nbase + warp_n * 32 + nf * 8 + (lane & 3) * 2;
                float v0 = acc[mf][nf][h * 2 + 0] + bv[nf].x;
                float v1 = acc[mf][nf][h * 2 + 1] + bv[nf].y;
                if (mode == M_PAIR) {
                    outp[(size_t)row * Nout + (nloc >> 1)] = __float2half(v0 * sigm(v1));
                } else {
                    if (mode == M_GATE) {
                        __half2 g = *(const __half2*)&aux[(size_t)row * N + nloc];
                        v0 *= sigm(__half2float(g.x));
                        v1 *= sigm(__half2float(g.y));
                    } else if (mode == M_SILU) {
                        v0 *= sigm(v0); v1 *= sigm(v1);
                    }
                    __half2 o; o.x = __float2half(v0); o.y = __float2half(v1);
                    *(__half2*)&outp[(size_t)row * Nloc + nloc] = o;
                }
            }
        }
    }
}

// ---------------- mega conversion kernel (one launch) --------------------------
// Segments (element offsets, all multiples of 4):
#define C0 (SEQ*INP)                 // xh
#define C1 (C0 + HYP*INP)            // w_in -> w15[0]
#define C2 (C1 + HIDN*INP)           // w2   -> w15[HYP*INP]
#define C3 (C2 + 2*HYP*HYP)          // interleave wg0/wg0g -> wI
#define C4 (C3 + HYP*HYP)            // wg_sh -> wshh
#define C5 (C4 + HIDN*HYP)           // w_h  -> whh
#define CVT_THREADS ((C5)/4)

__device__ __forceinline__ void cvt4(const float* s, __half* d) {
    float4 v = *(const float4*)s;
    __half2 a; a.x = __float2half(v.x); a.y = __float2half(v.y);
    __half2 b; b.x = __float2half(v.z); b.y = __float2half(v.w);
    *(__half2*)d       = a;
    *(__half2*)(d + 2) = b;
}

__global__ void mega_cvt(const float* __restrict__ x,    const float* __restrict__ w_in,
                         const float* __restrict__ w2,   const float* __restrict__ wg0,
                         const float* __restrict__ wg0g, const float* __restrict__ wg_sh,
                         const float* __restrict__ w_h,
                         __half* __restrict__ xh, __half* __restrict__ w15,
                         __half* __restrict__ wI, __half* __restrict__ wshh,
                         __half* __restrict__ whh)
{
    int i = (blockIdx.x * blockDim.x + threadIdx.x) * 4;
    if (i < C0) {
        cvt4(x + i, xh + i);
    } else if (i < C1) {
        int j = i - C0; cvt4(w_in + j, w15 + j);
    } else if (i < C2) {
        int j = i - C1; cvt4(w2 + j, w15 + HYP*INP + j);
    } else if (i < C3) {
        int j = i - C2;                    // interleaved rows of length HYP
        int r = j >> 10, k = j & (HYP - 1);
        const float* s = (r & 1) ? wg0g : wg0;
        cvt4(s + ((size_t)(r >> 1) << 10) + k, wI + j);
    } else if (i < C4) {
        int j = i - C3; cvt4(wg_sh + j, wshh + j);
    } else if (i < C5) {
        int j = i - C4; cvt4(w_h + j, whh + j);
    }
}

// ---------------- rotated-frame relu scan (fp16 B) ----------------------------
__global__ void scan_pass1(const __half* __restrict__ B,
                           float* __restrict__ Ac, float* __restrict__ Bc)
{
    int t    = blockIdx.x * blockDim.x + threadIdx.x;
    int lane = t & (HIDN - 1);
    int chnk = t >> 12;
    float Aa = -1e30f, Ss = 0.f;
    int base = chnk * CHUNK;
#pragma unroll 8
    for (int i = 0; i < CHUNK; i++) {
        int row = base + i;
        float b = __half2float(B[(size_t)row * HIDN + ((lane + row) & (HIDN - 1))]);
        Aa = fmaxf(0.f, b + Aa);
        Ss += b;
    }
    Ac[t] = Aa; Bc[t] = Ss;
}

__global__ void scan_combine(const float* __restrict__ hidden,
                             const float* __restrict__ Ac, const float* __restrict__ Bc,
                             float* __restrict__ Gb)
{
    int lane = blockIdx.x * blockDim.x + threadIdx.x;
    float gv = hidden[(lane - 1) & (HIDN - 1)];
    Gb[lane] = gv;
    for (int c = 0; c < NCHUNK; c++) {
        gv = fmaxf(Ac[c * HIDN + lane], Bc[c * HIDN + lane] + gv);
        Gb[(c + 1) * HIDN + lane] = gv;
    }
}

__global__ void scan_pass2(const __half* __restrict__ B, const float* __restrict__ Gb,
                           float* __restrict__ out, float* __restrict__ hlast, int write_h)
{
    int t    = blockIdx.x * blockDim.x + threadIdx.x;
    int lane = t & (HIDN - 1);
    int chnk = t >> 12;
    float gv = Gb[chnk * HIDN + lane];
    int base = chnk * CHUNK;
#pragma unroll 4
    for (int i = 0; i < CHUNK; i++) {
        int row = base + i;
        int col = (lane + row) & (HIDN - 1);
        gv = fmaxf(0.f, __half2float(B[(size_t)row * HIDN + col]) + gv);
        out[(size_t)row * HIDN + col] = gv;
    }
    if (write_h && chnk == NCHUNK - 1)
        hlast[(lane - 1) & (HIDN - 1)] = gv;
}

// ---------------- launch ------------------------------------------------------
extern "C" void kernel_launch(void* const* d_in, const int* in_sizes, int n_in,
                              void* d_out, int out_size)
{
    const float* x      = (const float*)d_in[0];
    const float* hidden = (const float*)d_in[1];
    const float* w_in   = (const float*)d_in[2];
    const float* b_in   = (const float*)d_in[3];
    const float* wg0    = (const float*)d_in[4];
    const float* bg0    = (const float*)d_in[5];
    const float* wg0g   = (const float*)d_in[6];
    const float* bg0g   = (const float*)d_in[7];
    const float* wg_sh  = (const float*)d_in[8];
    const float* bg_sh  = (const float*)d_in[9];
    const float* w_h    = (const float*)d_in[10];
    const float* b_h    = (const float*)d_in[11];
    const float* w2     = (const float*)d_in[12];
    const float* b2     = (const float*)d_in[13];

    float* out   = (float*)d_out;
    float* hlast = out + (size_t)SEQ * HIDN;
    int write_h  = (out_size >= SEQ * HIDN + HIDN) ? 1 : 0;

    cudaFuncSetAttribute(gemm_f16, cudaFuncAttributeMaxDynamicSharedMemorySize, SMEM_DYN);

    __half *xh, *h1h, *h2h, *h3h, *Gh, *Bh, *w15, *wI, *wshh, *whh;
    float *Ac, *Bc, *Gb;
    cudaGetSymbolAddress((void**)&xh,  g_xh);
    cudaGetSymbolAddress((void**)&h1h, g_h1h);
    cudaGetSymbolAddress((void**)&h2h, g_h2h);
    cudaGetSymbolAddress((void**)&h3h, g_h3h);
    cudaGetSymbolAddress((void**)&Gh,  g_Gh);
    cudaGetSymbolAddress((void**)&Bh,  g_Bh);
    cudaGetSymbolAddress((void**)&w15,  g_w15);
    cudaGetSymbolAddress((void**)&wI,   g_wI);
    cudaGetSymbolAddress((void**)&wshh, g_wshh);
    cudaGetSymbolAddress((void**)&whh,  g_whh);
    cudaGetSymbolAddress((void**)&Ac, g_Ac);
    cudaGetSymbolAddress((void**)&Bc, g_Bc);
    cudaGetSymbolAddress((void**)&Gb, g_Gb);

    // all conversions in one launch
    mega_cvt<<<(CVT_THREADS + 255)/256, 256>>>(x, w_in, w2, wg0, wg0g, wg_sh, w_h,
                                               xh, w15, wI, wshh, whh);

    const dim3 gDual((HYP + HIDN) / BN, SEQ / BM);   // 40 x 64
    const dim3 gPair(2*HYP / BN,        SEQ / BM);   // 16 x 64
    const dim3 gHyp (HYP / BN,          SEQ / BM);   //  8 x 64
    const dim3 gHid (HIDN / BN,         SEQ / BM);   // 32 x 64

    // [h1 ; G] = x @ [w_in ; w2]^T + [b_in ; b2]   (one merged GEMM)
    gemm_f16<<<gDual, 256, SMEM_DYN>>>(xh, w15, b_in, b2, nullptr,
                                       HYP + HIDN, INP, HYP, M_DUAL, h1h, Gh);
    // h2 = (h1 @ wg0^T + bg0) * sigmoid(h1 @ wg0g^T + bg0g)  [interleaved pair]
    gemm_f16<<<gPair, 256, SMEM_DYN>>>(h1h, wI, bg0, bg0g, nullptr,
                                       2*HYP, HYP, HYP, M_PAIR, h2h, nullptr);
    // h3 = silu(h2 @ wg_sh^T + bg_sh)
    gemm_f16<<<gHyp, 256, SMEM_DYN>>>(h2h, wshh, bg_sh, nullptr, nullptr,
                                      HYP, HYP, HYP, M_SILU, h3h, nullptr);
    // B = (h3 @ w_h^T + b_h) * sigmoid(G)
    gemm_f16<<<gHid, 256, SMEM_DYN>>>(h3h, whh, b_h, nullptr, Gh,
                                      HIDN, HYP, HIDN, M_GATE, Bh, nullptr);

    // chunked rotated-frame scan
    scan_pass1 <<<NCHUNK*HIDN/256, 256>>>(Bh, Ac, Bc);
    scan_combine<<<HIDN/256, 256>>>(hidden, Ac, Bc, Gb);
    scan_pass2 <<<NCHUNK*HIDN/256, 256>>>(Bh, Gb, out, hlast, write_h);
}